// round 3
// baseline (speedup 1.0000x reference)
#include <cuda_runtime.h>
#include <cstddef>

#define OUT0 131072 // 1024*128, offset of out_dis in d_out

// ---------------- scratch (device globals; no allocation allowed) -------------
__device__ float g_qk[1024 * 512];            // [B*L][INNER]
__device__ float g_cqk[8192 * 512];           // [B*P][INNER]
__device__ float g_cv[8192 * 512];            // [B*P][INNER]
__device__ float g_sim[16 * 16 * 64 * 512];   // [b][h][l][p] (scaled)
__device__ float g_probs[16 * 32 * 64 * 512]; // [b][c][l][p]
__device__ float g_outpre[1024 * 512];        // [B*L][INNER]
__device__ float g_wfold[64 * 64];            // Wpe2 @ W1[16:32]
__device__ float g_bfold[64];                 // bpe2 @ W1[16:32]

// mish(x) = x*tanh(softplus(x)) = x * u/(u+2), u = e^x*(e^x+2)  (exact identity)
__device__ __forceinline__ float mishf(float x) {
    float t = __expf(fminf(x, 8.0f));
    float u = t * (t + 2.0f);
    return x * __fdividef(u, u + 2.0f);
}

__device__ __forceinline__ float tf32r(float x) {
    unsigned u;
    asm("cvt.rna.tf32.f32 %0, %1;" : "=r"(u) : "f"(x));
    return __uint_as_float(u);
}

__device__ __forceinline__ void mma8(float* c, unsigned a0, unsigned a1,
                                     unsigned a2, unsigned a3,
                                     unsigned b0, unsigned b1) {
    asm volatile(
        "mma.sync.aligned.m16n8k8.row.col.f32.tf32.tf32.f32 "
        "{%0,%1,%2,%3},{%4,%5,%6,%7},{%8,%9},{%0,%1,%2,%3};"
        : "+f"(c[0]), "+f"(c[1]), "+f"(c[2]), "+f"(c[3])
        : "r"(a0), "r"(a1), "r"(a2), "r"(a3), "r"(b0), "r"(b1));
}

// ---------------- fold: Wfold = Wpe2 @ W1[16:32], bfold = bpe2 @ W1[16:32] ----
__global__ void fold_kernel(const float* __restrict__ w_pe2,
                            const float* __restrict__ b_pe2,
                            const float* __restrict__ w_mlp1)
{
    int tid = threadIdx.x;
    for (int e = tid; e < 4096; e += 256) {
        int kk = e >> 6, j = e & 63;
        float a = 0.f;
#pragma unroll
        for (int i = 0; i < 16; ++i)
            a += w_pe2[kk * 16 + i] * w_mlp1[(16 + i) * 64 + j];
        g_wfold[e] = a;
    }
    if (tid < 64) {
        float a = 0.f;
#pragma unroll
        for (int i = 0; i < 16; ++i)
            a += b_pe2[i] * w_mlp1[(16 + i) * 64 + tid];
        g_bfold[tid] = a;
    }
}

// ---------------- tf32 tensor-core GEMM: C[M,N] = A[M,K] @ B[K,N] -------------
__global__ void __launch_bounds__(256) tgemm_k(
    const float* __restrict__ A, const float* __restrict__ Bm,
    float* __restrict__ C, int M, int N, int K)
{
    __shared__ float As[128][36];
    __shared__ float Bs[32][136];
    const int tid = threadIdx.x;
    const int lane = tid & 31, warp = tid >> 5;
    const int wm = warp >> 1, wn = warp & 1;
    const int g = lane >> 2, t = lane & 3;
    const int row0 = blockIdx.y * 128, col0 = blockIdx.x * 128;

    float acc[2][8][4];
#pragma unroll
    for (int mt = 0; mt < 2; ++mt)
#pragma unroll
        for (int nt = 0; nt < 8; ++nt)
#pragma unroll
            for (int q = 0; q < 4; ++q) acc[mt][nt][q] = 0.f;

    for (int k0 = 0; k0 < K; k0 += 32) {
        float4 va[4], vb[4];
#pragma unroll
        for (int i = 0; i < 4; ++i) {
            int f4 = tid + i * 256;
            int r = f4 >> 3, kc = (f4 & 7) * 4;
            va[i] = *(const float4*)&A[(size_t)(row0 + r) * K + k0 + kc];
            int kk = f4 >> 5, nc = (f4 & 31) * 4;
            vb[i] = *(const float4*)&Bm[(size_t)(k0 + kk) * N + col0 + nc];
        }
        __syncthreads();
#pragma unroll
        for (int i = 0; i < 4; ++i) {
            int f4 = tid + i * 256;
            int r = f4 >> 3, kc = (f4 & 7) * 4;
            As[r][kc + 0] = tf32r(va[i].x);
            As[r][kc + 1] = tf32r(va[i].y);
            As[r][kc + 2] = tf32r(va[i].z);
            As[r][kc + 3] = tf32r(va[i].w);
            int kk = f4 >> 5, nc = (f4 & 31) * 4;
            Bs[kk][nc + 0] = tf32r(vb[i].x);
            Bs[kk][nc + 1] = tf32r(vb[i].y);
            Bs[kk][nc + 2] = tf32r(vb[i].z);
            Bs[kk][nc + 3] = tf32r(vb[i].w);
        }
        __syncthreads();
#pragma unroll
        for (int ks = 0; ks < 4; ++ks) {
            const int kb = ks * 8;
            unsigned a[2][4];
#pragma unroll
            for (int mt = 0; mt < 2; ++mt) {
                int rb = wm * 32 + mt * 16;
                a[mt][0] = __float_as_uint(As[rb + g][kb + t]);
                a[mt][1] = __float_as_uint(As[rb + g + 8][kb + t]);
                a[mt][2] = __float_as_uint(As[rb + g][kb + t + 4]);
                a[mt][3] = __float_as_uint(As[rb + g + 8][kb + t + 4]);
            }
#pragma unroll
            for (int nt = 0; nt < 8; ++nt) {
                int nb = wn * 64 + nt * 8;
                unsigned b0 = __float_as_uint(Bs[kb + t][nb + g]);
                unsigned b1 = __float_as_uint(Bs[kb + t + 4][nb + g]);
#pragma unroll
                for (int mt = 0; mt < 2; ++mt)
                    mma8(acc[mt][nt], a[mt][0], a[mt][1], a[mt][2], a[mt][3], b0, b1);
            }
        }
    }
#pragma unroll
    for (int mt = 0; mt < 2; ++mt) {
#pragma unroll
        for (int nt = 0; nt < 8; ++nt) {
            int r = row0 + wm * 32 + mt * 16 + g;
            int c = col0 + wn * 64 + nt * 8 + 2 * t;
            *(float2*)&C[(size_t)r * N + c] = make_float2(acc[mt][nt][0], acc[mt][nt][1]);
            *(float2*)&C[(size_t)(r + 8) * N + c] = make_float2(acc[mt][nt][2], acc[mt][nt][3]);
        }
    }
}

// ---------------- fp32 SIMT SGEMM (final out-proj, +bias) ---------------------
template <int BIAS>
__global__ void __launch_bounds__(256) sgemm_k(
    const float* __restrict__ A, const float* __restrict__ B,
    const float* __restrict__ bias, float* __restrict__ C,
    int M, int N, int K)
{
    __shared__ float As[8][128];
    __shared__ float Bs[8][128];
    const int t  = threadIdx.x;
    const int tx = t & 15, ty = t >> 4;
    const int row0 = blockIdx.y * 128, col0 = blockIdx.x * 128;

    float acc[8][8];
#pragma unroll
    for (int i = 0; i < 8; ++i)
#pragma unroll
        for (int j = 0; j < 8; ++j) acc[i][j] = 0.f;

    const int aRow = t >> 1, aCol = (t & 1) * 4;
    const int bRow = t >> 5, bCol = (t & 31) * 4;
    const float* Aptr = A + (size_t)(row0 + aRow) * K + aCol;
    const float* Bptr = B + (size_t)bRow * N + col0 + bCol;

    for (int k0 = 0; k0 < K; k0 += 8) {
        float4 av = *(const float4*)(Aptr + k0);
        float4 bv = *(const float4*)(Bptr + (size_t)k0 * N);
        __syncthreads();
        As[aCol + 0][aRow] = av.x;
        As[aCol + 1][aRow] = av.y;
        As[aCol + 2][aRow] = av.z;
        As[aCol + 3][aRow] = av.w;
        *(float4*)&Bs[bRow][bCol] = bv;
        __syncthreads();
#pragma unroll
        for (int kk = 0; kk < 8; ++kk) {
            float a[8], bb[8];
            *(float4*)&a[0]  = *(const float4*)&As[kk][ty * 8];
            *(float4*)&a[4]  = *(const float4*)&As[kk][ty * 8 + 4];
            *(float4*)&bb[0] = *(const float4*)&Bs[kk][tx * 8];
            *(float4*)&bb[4] = *(const float4*)&Bs[kk][tx * 8 + 4];
#pragma unroll
            for (int i = 0; i < 8; ++i)
#pragma unroll
                for (int j = 0; j < 8; ++j) acc[i][j] += a[i] * bb[j];
        }
    }
#pragma unroll
    for (int i = 0; i < 8; ++i) {
        int r = row0 + ty * 8 + i;
#pragma unroll
        for (int j4 = 0; j4 < 2; ++j4) {
            int c = col0 + tx * 8 + j4 * 4;
            float4 v;
            v.x = acc[i][j4 * 4 + 0];
            v.y = acc[i][j4 * 4 + 1];
            v.z = acc[i][j4 * 4 + 2];
            v.w = acc[i][j4 * 4 + 3];
            if (BIAS) {
                v.x += bias[c + 0]; v.y += bias[c + 1];
                v.z += bias[c + 2]; v.w += bias[c + 3];
            }
            *(float4*)&C[(size_t)r * N + c] = v;
        }
    }
}

// ---------------- sim via tf32 mma: per (p-half, h, b) 64x256x32 --------------
__global__ void __launch_bounds__(256) sim_mma_kernel()
{
    __shared__ float As[64 * 34];   // [l][d]
    __shared__ float Bs[32 * 258];  // [d][p] (transposed)
    const int ph = blockIdx.x, h = blockIdx.y, b = blockIdx.z;
    const int tid = threadIdx.x;
    const int w = tid >> 5, lane = tid & 31, g = lane >> 2, t = lane & 3;

    for (int e = tid; e < 2048; e += 256) {
        int lr = e >> 5, d = e & 31;
        As[lr * 34 + d] = tf32r(g_qk[((size_t)(b * 64 + lr)) * 512 + h * 32 + d]);
    }
    for (int e = tid; e < 8192; e += 256) {
        int p = e >> 5, d = e & 31;
        Bs[d * 258 + p] = tf32r(g_cqk[((size_t)(b * 512 + ph * 256 + p)) * 512 + h * 32 + d]);
    }
    __syncthreads();

    float acc[4][4][4];
#pragma unroll
    for (int mi = 0; mi < 4; ++mi)
#pragma unroll
        for (int nt = 0; nt < 4; ++nt)
#pragma unroll
            for (int q = 0; q < 4; ++q) acc[mi][nt][q] = 0.f;

    const int n0 = w * 32;
#pragma unroll
    for (int kt = 0; kt < 4; ++kt) {
        const int kb = kt * 8;
        unsigned aF[4][4];
#pragma unroll
        for (int mi = 0; mi < 4; ++mi) {
            int rA = mi * 16;
            aF[mi][0] = __float_as_uint(As[(rA + g) * 34 + kb + t]);
            aF[mi][1] = __float_as_uint(As[(rA + g + 8) * 34 + kb + t]);
            aF[mi][2] = __float_as_uint(As[(rA + g) * 34 + kb + t + 4]);
            aF[mi][3] = __float_as_uint(As[(rA + g + 8) * 34 + kb + t + 4]);
        }
#pragma unroll
        for (int nt = 0; nt < 4; ++nt) {
            int nb = n0 + nt * 8;
            unsigned b0 = __float_as_uint(Bs[(kb + t) * 258 + nb + g]);
            unsigned b1 = __float_as_uint(Bs[(kb + t + 4) * 258 + nb + g]);
#pragma unroll
            for (int mi = 0; mi < 4; ++mi)
                mma8(acc[mi][nt], aF[mi][0], aF[mi][1], aF[mi][2], aF[mi][3], b0, b1);
        }
    }
    const float SCALE = 0.17677669529663687f; // 32^-0.5
#pragma unroll
    for (int mi = 0; mi < 4; ++mi)
#pragma unroll
        for (int nt = 0; nt < 4; ++nt) {
            int lr = mi * 16 + g;
            int pc = ph * 256 + n0 + nt * 8 + 2 * t;
            size_t base = (((size_t)(b * 16 + h)) * 64 + lr) * 512 + pc;
            *(float2*)&g_sim[base] =
                make_float2(acc[mi][nt][0] * SCALE, acc[mi][nt][1] * SCALE);
            *(float2*)&g_sim[base + (size_t)8 * 512] =
                make_float2(acc[mi][nt][2] * SCALE, acc[mi][nt][3] * SCALE);
        }
}

// ---------------- fused pairwise: PE(scalar) + MLP(mma) + softmax -------------
// smem layout (floats)
#define LG_OFF   0
#define LG_SZ    (512 * 34)
#define MS_OFF   (LG_OFF + LG_SZ)        // [128][66] A-operand, PE-hidden (tf32)
#define MS_SZ    (128 * 66)
#define HS_OFF   (MS_OFF + MS_SZ)        // [128][66] A-operand, mish hidden (tf32)
#define HS_SZ    (128 * 66)
#define XS_OFF   (HS_OFF + HS_SZ)        // [128][18] A-operand, sim part (tf32)
#define XS_SZ    (128 * 18)
#define W1U_OFF  (XS_OFF + XS_SZ)        // [16][66] B-operand
#define W1U_SZ   (16 * 66)
#define WF_OFF   (W1U_OFF + W1U_SZ)      // [64][66] B-operand
#define WF_SZ    (64 * 66)
#define W2_OFF   (WF_OFF + WF_SZ)        // [64][34] B-operand
#define W2_SZ    (64 * 34)
#define WPE1_OFF (W2_OFF + W2_SZ)        // [64][4]
#define BPE1_OFF (WPE1_OFF + 256)
#define BFOLD_OFF (BPE1_OFF + 64)
#define BM2_OFF  (BFOLD_OFF + 64)
#define PAIR_SM_FLOATS (BM2_OFF + 32)

__global__ void __launch_bounds__(512) pair_kernel(
    const float* __restrict__ xp, const float* __restrict__ xl,
    const float* __restrict__ w_mlp1, const float* __restrict__ w_mlp2,
    const float* __restrict__ b_mlp2, const float* __restrict__ sigma,
    const float* __restrict__ w_pe1, const float* __restrict__ b_pe1)
{
    extern __shared__ float sm[];
    float* lg    = sm + LG_OFF;
    float* Ms    = sm + MS_OFF;
    float* Hs    = sm + HS_OFF;
    float* Xs    = sm + XS_OFF;
    float* W1U   = sm + W1U_OFF;
    float* WF    = sm + WF_OFF;
    float* W2S   = sm + W2_OFF;
    float* WPE1  = sm + WPE1_OFF;
    float* BPE1  = sm + BPE1_OFF;
    float* BFOLD = sm + BFOLD_OFF;
    float* BM2   = sm + BM2_OFF;

    const int tid = threadIdx.x;
    const int l = blockIdx.x, b = blockIdx.y;
    const int w = tid >> 5, lane = tid & 31, g = lane >> 2, t = lane & 3;

    // stage weights
    for (int e = tid; e < 1024; e += 512) { int k = e >> 6, n = e & 63; W1U[k * 66 + n] = tf32r(w_mlp1[e]); }
    for (int e = tid; e < 4096; e += 512) { int k = e >> 6, n = e & 63; WF[k * 66 + n] = tf32r(g_wfold[e]); }
    for (int e = tid; e < 2048; e += 512) { int k = e >> 5, n = e & 31; W2S[k * 34 + n] = tf32r(w_mlp2[e]); }
    if (tid < 192) { int i = tid >> 6, k = tid & 63; WPE1[k * 4 + i] = w_pe1[tid]; }
    if (tid < 64) BPE1[tid] = b_pe1[tid];
    if (tid < 64) BFOLD[tid] = g_bfold[tid];
    if (tid < 32) BM2[tid] = b_mlp2[tid];

    const float sg = sigma[0];
    const float cpe = -0.5f / (sg * sg);
    const float xl0 = xl[(size_t)(b * 64 + l) * 3 + 0];
    const float xl1 = xl[(size_t)(b * 64 + l) * 3 + 1];
    const float xl2 = xl[(size_t)(b * 64 + l) * 3 + 2];

    const int r  = tid & 127;   // row within chunk
    const int kg = tid >> 7;    // 0..3 quarter
    __syncthreads();

    for (int ch = 0; ch < 4; ++ch) {
        // ---- PE layer1 (scalar) + sim staging ----
        {
            int p = ch * 128 + r;
            const float* xpr = xp + (size_t)(b * 512 + p) * 3;
            float pe0 = __expf(cpe * (xpr[0] - xl0));
            float pe1 = __expf(cpe * (xpr[1] - xl1));
            float pe2 = __expf(cpe * (xpr[2] - xl2));
#pragma unroll
            for (int q = 0; q < 16; ++q) {
                int kk = kg * 16 + q;
                float hk = BPE1[kk] + pe0 * WPE1[kk * 4] + pe1 * WPE1[kk * 4 + 1]
                         + pe2 * WPE1[kk * 4 + 2];
                Ms[r * 66 + kk] = tf32r(mishf(hk));
            }
#pragma unroll
            for (int q = 0; q < 4; ++q) {
                int h = kg * 4 + q;
                Xs[r * 18 + h] =
                    tf32r(g_sim[(((size_t)b * 16 + h) * 64 + l) * 512 + p]);
            }
        }
        __syncthreads();

        // ---- layer1: hidden[128][64] = Xs@W1U + Ms@WF + bfold; mish -> Hs ----
        {
            const int mi = w >> 1, nh = w & 1;
            const int rA = mi * 16;
            float acc[4][4];
#pragma unroll
            for (int nt = 0; nt < 4; ++nt) {
                int nb = nh * 32 + nt * 8;
                float f0 = BFOLD[nb + 2 * t], f1 = BFOLD[nb + 2 * t + 1];
                acc[nt][0] = f0; acc[nt][1] = f1; acc[nt][2] = f0; acc[nt][3] = f1;
            }
#pragma unroll
            for (int kt = 0; kt < 2; ++kt) {
                int kb = kt * 8;
                unsigned a0 = __float_as_uint(Xs[(rA + g) * 18 + kb + t]);
                unsigned a1 = __float_as_uint(Xs[(rA + g + 8) * 18 + kb + t]);
                unsigned a2 = __float_as_uint(Xs[(rA + g) * 18 + kb + t + 4]);
                unsigned a3 = __float_as_uint(Xs[(rA + g + 8) * 18 + kb + t + 4]);
#pragma unroll
                for (int nt = 0; nt < 4; ++nt) {
                    int nb = nh * 32 + nt * 8;
                    unsigned b0 = __float_as_uint(W1U[(kb + t) * 66 + nb + g]);
                    unsigned b1 = __float_as_uint(W1U[(kb + t + 4) * 66 + nb + g]);
                    mma8(acc[nt], a0, a1, a2, a3, b0, b1);
                }
            }
#pragma unroll
            for (int kt = 0; kt < 8; ++kt) {
                int kb = kt * 8;
                unsigned a0 = __float_as_uint(Ms[(rA + g) * 66 + kb + t]);
                unsigned a1 = __float_as_uint(Ms[(rA + g + 8) * 66 + kb + t]);
                unsigned a2 = __float_as_uint(Ms[(rA + g) * 66 + kb + t + 4]);
                unsigned a3 = __float_as_uint(Ms[(rA + g + 8) * 66 + kb + t + 4]);
#pragma unroll
                for (int nt = 0; nt < 4; ++nt) {
                    int nb = nh * 32 + nt * 8;
                    unsigned b0 = __float_as_uint(WF[(kb + t) * 66 + nb + g]);
                    unsigned b1 = __float_as_uint(WF[(kb + t + 4) * 66 + nb + g]);
                    mma8(acc[nt], a0, a1, a2, a3, b0, b1);
                }
            }
#pragma unroll
            for (int nt = 0; nt < 4; ++nt) {
                int c0 = nh * 32 + nt * 8 + 2 * t;
                *(float2*)&Hs[(rA + g) * 66 + c0] =
                    make_float2(tf32r(mishf(acc[nt][0])), tf32r(mishf(acc[nt][1])));
                *(float2*)&Hs[(rA + g + 8) * 66 + c0] =
                    make_float2(tf32r(mishf(acc[nt][2])), tf32r(mishf(acc[nt][3])));
            }
        }
        __syncthreads();

        // ---- layer2: logits[128][32] = Hs@W2 + b2 -> lg ----
        {
            const int mi2 = w >> 1, np = w & 1;
            float acc2[2][4];
#pragma unroll
            for (int j = 0; j < 2; ++j) {
                int nb = (np * 2 + j) * 8;
                float f0 = BM2[nb + 2 * t], f1 = BM2[nb + 2 * t + 1];
                acc2[j][0] = f0; acc2[j][1] = f1; acc2[j][2] = f0; acc2[j][3] = f1;
            }
#pragma unroll
            for (int kt = 0; kt < 8; ++kt) {
                int kb = kt * 8;
                unsigned a0 = __float_as_uint(Hs[(mi2 * 16 + g) * 66 + kb + t]);
                unsigned a1 = __float_as_uint(Hs[(mi2 * 16 + g + 8) * 66 + kb + t]);
                unsigned a2 = __float_as_uint(Hs[(mi2 * 16 + g) * 66 + kb + t + 4]);
                unsigned a3 = __float_as_uint(Hs[(mi2 * 16 + g + 8) * 66 + kb + t + 4]);
#pragma unroll
                for (int j = 0; j < 2; ++j) {
                    int nb = (np * 2 + j) * 8;
                    unsigned b0 = __float_as_uint(W2S[(kb + t) * 34 + nb + g]);
                    unsigned b1 = __float_as_uint(W2S[(kb + t + 4) * 34 + nb + g]);
                    mma8(acc2[j], a0, a1, a2, a3, b0, b1);
                }
            }
            int pr = ch * 128 + mi2 * 16;
#pragma unroll
            for (int j = 0; j < 2; ++j) {
                int c0 = (np * 2 + j) * 8 + 2 * t;
                *(float2*)&lg[(pr + g) * 34 + c0] = make_float2(acc2[j][0], acc2[j][1]);
                *(float2*)&lg[(pr + g + 8) * 34 + c0] = make_float2(acc2[j][2], acc2[j][3]);
            }
        }
        __syncthreads();
    }

    // ---- softmax over p per channel; warp w handles channels 2w, 2w+1 ----
#pragma unroll
    for (int cc = 0; cc < 2; ++cc) {
        int c = w * 2 + cc;
        float mx = -3.4e38f;
#pragma unroll
        for (int i = 0; i < 16; ++i) mx = fmaxf(mx, lg[(lane + i * 32) * 34 + c]);
#pragma unroll
        for (int off = 16; off; off >>= 1) mx = fmaxf(mx, __shfl_xor_sync(0xffffffffu, mx, off));
        float ev[16]; float sum = 0.f;
#pragma unroll
        for (int i = 0; i < 16; ++i) {
            ev[i] = __expf(lg[(lane + i * 32) * 34 + c] - mx);
            sum += ev[i];
        }
#pragma unroll
        for (int off = 16; off; off >>= 1) sum += __shfl_xor_sync(0xffffffffu, sum, off);
        float inv = 1.0f / sum;
        size_t base = (((size_t)b * 32 + c) * 64 + l) * 512;
#pragma unroll
        for (int i = 0; i < 16; ++i) g_probs[base + lane + i * 32] = ev[i] * inv;
    }
}

// ---------------- out_pre[b,l,h,d] = sum_p probs[b,h,l,p] * cv[b,p,h,d] --------
__global__ void __launch_bounds__(256) outagg_kernel()
{
    const int b = blockIdx.x, h = blockIdx.y;
    __shared__ float Acs[64][128];
    __shared__ float Bcs[128][32];
    const int tid = threadIdx.x;
    const int d = tid & 31, lgp = tid >> 5, l0 = lgp * 8;
    float acc[8];
#pragma unroll
    for (int j = 0; j < 8; ++j) acc[j] = 0.f;

    for (int pc = 0; pc < 512; pc += 128) {
        __syncthreads();
        for (int e = tid; e < 2048; e += 256) {
            int l = e >> 5, pq = (e & 31) * 4;
            *(float4*)&Acs[l][pq] =
                *(const float4*)&g_probs[(((size_t)b * 32 + h) * 64 + l) * 512 + pc + pq];
        }
        for (int e = tid; e < 1024; e += 256) {
            int p = e >> 3, d4 = (e & 7) * 4;
            *(float4*)&Bcs[p][d4] =
                *(const float4*)&g_cv[((size_t)(b * 512 + pc + p)) * 512 + h * 32 + d4];
        }
        __syncthreads();
        for (int p = 0; p < 128; p += 4) {
            float bv0 = Bcs[p][d], bv1 = Bcs[p + 1][d], bv2 = Bcs[p + 2][d], bv3 = Bcs[p + 3][d];
#pragma unroll
            for (int j = 0; j < 8; ++j) {
                float4 a = *(const float4*)&Acs[l0 + j][p];
                acc[j] += a.x * bv0 + a.y * bv1 + a.z * bv2 + a.w * bv3;
            }
        }
    }
#pragma unroll
    for (int j = 0; j < 8; ++j)
        g_outpre[((size_t)(b * 64 + l0 + j)) * 512 + h * 32 + d] = acc[j];
}

// ---------------- distance path: aggregate + tiny MLP -------------------------
__global__ void __launch_bounds__(256) disagg_kernel(
    const float* __restrict__ xp, const float* __restrict__ xl,
    const float* __restrict__ w_dis1, const float* __restrict__ b_dis1,
    const float* __restrict__ w_dis2, const float* __restrict__ b_dis2,
    float* __restrict__ out)
{
    const int l = blockIdx.x, b = blockIdx.y;
    __shared__ float xps[512 * 3];
    __shared__ float ods[3][16];
    __shared__ float zs[3][32];
    const int tid = threadIdx.x;
    for (int e = tid; e < 1536; e += 256) xps[e] = xp[(size_t)b * 1536 + e];
    __syncthreads();

    const int w = tid >> 5, lane = tid & 31;
#pragma unroll
    for (int q = 0; q < 6; ++q) {
        int idx = w * 6 + q;
        int i = idx >> 4, h = idx & 15;
        size_t base = (((size_t)b * 32 + 16 + h) * 64 + l) * 512;
        float sum = 0.f;
#pragma unroll
        for (int it = 0; it < 16; ++it) {
            int p = lane + it * 32;
            sum += g_probs[base + p] * xps[p * 3 + i];
        }
#pragma unroll
        for (int off = 16; off; off >>= 1) sum += __shfl_xor_sync(0xffffffffu, sum, off);
        if (lane == 0) ods[i][h] = sum - xl[(size_t)(b * 64 + l) * 3 + i];
    }
    __syncthreads();
    if (tid < 96) {
        int i = tid >> 5, k = tid & 31;
        float hz = b_dis1[k];
#pragma unroll
        for (int j = 0; j < 16; ++j) hz += ods[i][j] * w_dis1[j * 32 + k];
        zs[i][k] = mishf(hz);
    }
    __syncthreads();
    if (tid < 48) {
        int i = tid / 16, h = tid % 16;
        float y = b_dis2[h];
#pragma unroll
        for (int k = 0; k < 32; ++k) y += zs[i][k] * w_dis2[k * 16 + h];
        out[OUT0 + (((size_t)b * 64 + l) * 3 + i) * 16 + h] = y;
    }
}

// ---------------- launch -------------------------------------------------------
extern "C" void kernel_launch(void* const* d_in, const int* in_sizes, int n_in,
                              void* d_out, int out_size)
{
    (void)in_sizes; (void)n_in; (void)out_size;
    const float* h_ligand = (const float*)d_in[0];
    const float* context  = (const float*)d_in[1];
    const float* xp       = (const float*)d_in[2];
    const float* xl       = (const float*)d_in[3];
    const float* w_qk     = (const float*)d_in[4];
    // d_in[5] = w_v (unused by the reference)
    const float* w_cqk    = (const float*)d_in[6];
    const float* w_cv     = (const float*)d_in[7];
    const float* w_mlp1   = (const float*)d_in[8];
    const float* w_mlp2   = (const float*)d_in[9];
    const float* b_mlp2   = (const float*)d_in[10];
    const float* w_out    = (const float*)d_in[11];
    const float* b_out    = (const float*)d_in[12];
    const float* w_dis1   = (const float*)d_in[13];
    const float* b_dis1   = (const float*)d_in[14];
    const float* w_dis2   = (const float*)d_in[15];
    const float* b_dis2   = (const float*)d_in[16];
    const float* sigma    = (const float*)d_in[17];
    const float* w_pe1    = (const float*)d_in[18];
    const float* b_pe1    = (const float*)d_in[19];
    const float* w_pe2    = (const float*)d_in[20];
    const float* b_pe2    = (const float*)d_in[21];
    float* out = (float*)d_out;

    void *p_qk, *p_cqk, *p_cv, *p_outpre;
    cudaGetSymbolAddress(&p_qk, g_qk);
    cudaGetSymbolAddress(&p_cqk, g_cqk);
    cudaGetSymbolAddress(&p_cv, g_cv);
    cudaGetSymbolAddress(&p_outpre, g_outpre);

    // fold PE layer2 into MLP1 lower half
    fold_kernel<<<1, 256>>>(w_pe2, b_pe2, w_mlp1);

    // projections (tf32 tensor cores)
    tgemm_k<<<dim3(4, 8), 256>>>(h_ligand, w_qk, (float*)p_qk, 1024, 512, 128);
    tgemm_k<<<dim3(4, 64), 256>>>(context, w_cqk, (float*)p_cqk, 8192, 512, 256);
    tgemm_k<<<dim3(4, 64), 256>>>(context, w_cv, (float*)p_cv, 8192, 512, 256);

    // similarity scores (tf32 mma)
    sim_mma_kernel<<<dim3(2, 16, 16), 256>>>();

    // fused pairwise: PE + MLP (mma) + softmax
    const int sm_bytes = PAIR_SM_FLOATS * (int)sizeof(float);
    cudaFuncSetAttribute(pair_kernel, cudaFuncAttributeMaxDynamicSharedMemorySize, sm_bytes);
    pair_kernel<<<dim3(64, 16), 512, sm_bytes>>>(xp, xl, w_mlp1, w_mlp2, b_mlp2,
                                                 sigma, w_pe1, b_pe1);

    // context path: attn @ cv, then out-proj (+bias, fp32) into d_out
    outagg_kernel<<<dim3(16, 16), 256>>>();
    sgemm_k<1><<<dim3(1, 8), 256>>>((const float*)p_outpre, w_out, b_out, out, 1024, 128, 512);

    // distance path into d_out
    disagg_kernel<<<dim3(64, 16), 256>>>(xp, xl, w_dis1, b_dis1, w_dis2, b_dis2, out);
}

// round 4
// speedup vs baseline: 1.1697x; 1.1697x over previous
#include <cuda_runtime.h>
#include <cstddef>

#define OUT0 131072 // 1024*128, offset of out_dis in d_out

typedef unsigned long long u64;

// ---------------- scratch (device globals; no allocation allowed) -------------
__device__ float g_qk[1024 * 512];            // [B*L][INNER]
__device__ float g_cqk[8192 * 512];           // [B*P][INNER]
__device__ float g_cv[8192 * 512];            // [B*P][INNER]
__device__ float g_sim[16 * 16 * 64 * 512];   // [b][h][l][p] (scaled)
__device__ float g_probs[16 * 32 * 64 * 512]; // [b][c][l][p]
__device__ float g_outpre[1024 * 512];        // [B*L][INNER]

// mish(x) = x*tanh(softplus(x)) = x * u/(u+2), u = e^x*(e^x+2)  (exact identity)
__device__ __forceinline__ float mishf(float x) {
    float t = __expf(fminf(x, 8.0f));
    float u = t * (t + 2.0f);
    return x * __fdividef(u, u + 2.0f);
}

__device__ __forceinline__ float tf32r(float x) {
    unsigned u;
    asm("cvt.rna.tf32.f32 %0, %1;" : "=r"(u) : "f"(x));
    return __uint_as_float(u);
}

__device__ __forceinline__ void mma8(float* c, unsigned a0, unsigned a1,
                                     unsigned a2, unsigned a3,
                                     unsigned b0, unsigned b1) {
    asm volatile(
        "mma.sync.aligned.m16n8k8.row.col.f32.tf32.tf32.f32 "
        "{%0,%1,%2,%3},{%4,%5,%6,%7},{%8,%9},{%0,%1,%2,%3};"
        : "+f"(c[0]), "+f"(c[1]), "+f"(c[2]), "+f"(c[3])
        : "r"(a0), "r"(a1), "r"(a2), "r"(a3), "r"(b0), "r"(b1));
}

// ---- packed f32x2 helpers (Blackwell FFMA2 — only reachable via PTX) ---------
__device__ __forceinline__ u64 ffma2(u64 a, u64 b, u64 c) {
    u64 d;
    asm("fma.rn.f32x2 %0, %1, %2, %3;" : "=l"(d) : "l"(a), "l"(b), "l"(c));
    return d;
}
__device__ __forceinline__ u64 pk2(float x, float y) {
    u64 r;
    asm("mov.b64 %0, {%1, %2};" : "=l"(r) : "f"(x), "f"(y));
    return r;
}
__device__ __forceinline__ float2 up2(u64 v) {
    float2 r;
    asm("mov.b64 {%0, %1}, %2;" : "=f"(r.x), "=f"(r.y) : "l"(v));
    return r;
}

// ---------------- tf32 tensor-core GEMM: C[M,N] = A[M,K] @ B[K,N] -------------
// DUAL=1: N logically 1024 split across two 512-wide weight/output pairs.
template <int DUAL>
__global__ void __launch_bounds__(256) tgemm_k(
    const float* __restrict__ A, const float* __restrict__ B0,
    const float* __restrict__ B1, float* __restrict__ C0,
    float* __restrict__ C1, int M, int N, int K)
{
    __shared__ float As[128][36];
    __shared__ float Bs[32][136];
    const int tid = threadIdx.x;
    const int lane = tid & 31, warp = tid >> 5;
    const int wm = warp >> 1, wn = warp & 1;
    const int g = lane >> 2, t = lane & 3;
    const int row0 = blockIdx.y * 128;
    int col0 = blockIdx.x * 128;
    const float* Bm = B0;
    float* C = C0;
    if (DUAL && col0 >= 512) { Bm = B1; C = C1; col0 -= 512; }

    float acc[2][8][4];
#pragma unroll
    for (int mt = 0; mt < 2; ++mt)
#pragma unroll
        for (int nt = 0; nt < 8; ++nt)
#pragma unroll
            for (int q = 0; q < 4; ++q) acc[mt][nt][q] = 0.f;

    for (int k0 = 0; k0 < K; k0 += 32) {
        float4 va[4], vb[4];
#pragma unroll
        for (int i = 0; i < 4; ++i) {
            int f4 = tid + i * 256;
            int r = f4 >> 3, kc = (f4 & 7) * 4;
            va[i] = *(const float4*)&A[(size_t)(row0 + r) * K + k0 + kc];
            int kk = f4 >> 5, nc = (f4 & 31) * 4;
            vb[i] = *(const float4*)&Bm[(size_t)(k0 + kk) * N + col0 + nc];
        }
        __syncthreads();
#pragma unroll
        for (int i = 0; i < 4; ++i) {
            int f4 = tid + i * 256;
            int r = f4 >> 3, kc = (f4 & 7) * 4;
            As[r][kc + 0] = tf32r(va[i].x);
            As[r][kc + 1] = tf32r(va[i].y);
            As[r][kc + 2] = tf32r(va[i].z);
            As[r][kc + 3] = tf32r(va[i].w);
            int kk = f4 >> 5, nc = (f4 & 31) * 4;
            Bs[kk][nc + 0] = tf32r(vb[i].x);
            Bs[kk][nc + 1] = tf32r(vb[i].y);
            Bs[kk][nc + 2] = tf32r(vb[i].z);
            Bs[kk][nc + 3] = tf32r(vb[i].w);
        }
        __syncthreads();
#pragma unroll
        for (int ks = 0; ks < 4; ++ks) {
            const int kb = ks * 8;
            unsigned a[2][4];
#pragma unroll
            for (int mt = 0; mt < 2; ++mt) {
                int rb = wm * 32 + mt * 16;
                a[mt][0] = __float_as_uint(As[rb + g][kb + t]);
                a[mt][1] = __float_as_uint(As[rb + g + 8][kb + t]);
                a[mt][2] = __float_as_uint(As[rb + g][kb + t + 4]);
                a[mt][3] = __float_as_uint(As[rb + g + 8][kb + t + 4]);
            }
#pragma unroll
            for (int nt = 0; nt < 8; ++nt) {
                int nb = wn * 64 + nt * 8;
                unsigned b0 = __float_as_uint(Bs[kb + t][nb + g]);
                unsigned b1 = __float_as_uint(Bs[kb + t + 4][nb + g]);
#pragma unroll
                for (int mt = 0; mt < 2; ++mt)
                    mma8(acc[mt][nt], a[mt][0], a[mt][1], a[mt][2], a[mt][3], b0, b1);
            }
        }
    }
#pragma unroll
    for (int mt = 0; mt < 2; ++mt) {
#pragma unroll
        for (int nt = 0; nt < 8; ++nt) {
            int r = row0 + wm * 32 + mt * 16 + g;
            int c = col0 + wn * 64 + nt * 8 + 2 * t;
            *(float2*)&C[(size_t)r * N + c] = make_float2(acc[mt][nt][0], acc[mt][nt][1]);
            *(float2*)&C[(size_t)(r + 8) * N + c] = make_float2(acc[mt][nt][2], acc[mt][nt][3]);
        }
    }
}

// ---------------- fp32 SIMT SGEMM (final out-proj, +bias) ---------------------
template <int BIAS>
__global__ void __launch_bounds__(256) sgemm_k(
    const float* __restrict__ A, const float* __restrict__ B,
    const float* __restrict__ bias, float* __restrict__ C,
    int M, int N, int K)
{
    __shared__ float As[8][128];
    __shared__ float Bs[8][128];
    const int t  = threadIdx.x;
    const int tx = t & 15, ty = t >> 4;
    const int row0 = blockIdx.y * 128, col0 = blockIdx.x * 128;

    float acc[8][8];
#pragma unroll
    for (int i = 0; i < 8; ++i)
#pragma unroll
        for (int j = 0; j < 8; ++j) acc[i][j] = 0.f;

    const int aRow = t >> 1, aCol = (t & 1) * 4;
    const int bRow = t >> 5, bCol = (t & 31) * 4;
    const float* Aptr = A + (size_t)(row0 + aRow) * K + aCol;
    const float* Bptr = B + (size_t)bRow * N + col0 + bCol;

    for (int k0 = 0; k0 < K; k0 += 8) {
        float4 av = *(const float4*)(Aptr + k0);
        float4 bv = *(const float4*)(Bptr + (size_t)k0 * N);
        __syncthreads();
        As[aCol + 0][aRow] = av.x;
        As[aCol + 1][aRow] = av.y;
        As[aCol + 2][aRow] = av.z;
        As[aCol + 3][aRow] = av.w;
        *(float4*)&Bs[bRow][bCol] = bv;
        __syncthreads();
#pragma unroll
        for (int kk = 0; kk < 8; ++kk) {
            float a[8], bb[8];
            *(float4*)&a[0]  = *(const float4*)&As[kk][ty * 8];
            *(float4*)&a[4]  = *(const float4*)&As[kk][ty * 8 + 4];
            *(float4*)&bb[0] = *(const float4*)&Bs[kk][tx * 8];
            *(float4*)&bb[4] = *(const float4*)&Bs[kk][tx * 8 + 4];
#pragma unroll
            for (int i = 0; i < 8; ++i)
#pragma unroll
                for (int j = 0; j < 8; ++j) acc[i][j] += a[i] * bb[j];
        }
    }
#pragma unroll
    for (int i = 0; i < 8; ++i) {
        int r = row0 + ty * 8 + i;
#pragma unroll
        for (int j4 = 0; j4 < 2; ++j4) {
            int c = col0 + tx * 8 + j4 * 4;
            float4 v;
            v.x = acc[i][j4 * 4 + 0];
            v.y = acc[i][j4 * 4 + 1];
            v.z = acc[i][j4 * 4 + 2];
            v.w = acc[i][j4 * 4 + 3];
            if (BIAS) {
                v.x += bias[c + 0]; v.y += bias[c + 1];
                v.z += bias[c + 2]; v.w += bias[c + 3];
            }
            *(float4*)&C[(size_t)r * N + c] = v;
        }
    }
}

// ---------------- sim via tf32 mma: per (p-half, h, b) 64x256x32 --------------
__global__ void __launch_bounds__(256) sim_mma_kernel()
{
    __shared__ float As[64 * 34];   // [l][d]
    __shared__ float Bs[32 * 258];  // [d][p] (transposed)
    const int ph = blockIdx.x, h = blockIdx.y, b = blockIdx.z;
    const int tid = threadIdx.x;
    const int w = tid >> 5, lane = tid & 31, g = lane >> 2, t = lane & 3;

    for (int e = tid; e < 2048; e += 256) {
        int lr = e >> 5, d = e & 31;
        As[lr * 34 + d] = tf32r(g_qk[((size_t)(b * 64 + lr)) * 512 + h * 32 + d]);
    }
    for (int e = tid; e < 8192; e += 256) {
        int p = e >> 5, d = e & 31;
        Bs[d * 258 + p] = tf32r(g_cqk[((size_t)(b * 512 + ph * 256 + p)) * 512 + h * 32 + d]);
    }
    __syncthreads();

    float acc[4][4][4];
#pragma unroll
    for (int mi = 0; mi < 4; ++mi)
#pragma unroll
        for (int nt = 0; nt < 4; ++nt)
#pragma unroll
            for (int q = 0; q < 4; ++q) acc[mi][nt][q] = 0.f;

    const int n0 = w * 32;
#pragma unroll
    for (int kt = 0; kt < 4; ++kt) {
        const int kb = kt * 8;
        unsigned aF[4][4];
#pragma unroll
        for (int mi = 0; mi < 4; ++mi) {
            int rA = mi * 16;
            aF[mi][0] = __float_as_uint(As[(rA + g) * 34 + kb + t]);
            aF[mi][1] = __float_as_uint(As[(rA + g + 8) * 34 + kb + t]);
            aF[mi][2] = __float_as_uint(As[(rA + g) * 34 + kb + t + 4]);
            aF[mi][3] = __float_as_uint(As[(rA + g + 8) * 34 + kb + t + 4]);
        }
#pragma unroll
        for (int nt = 0; nt < 4; ++nt) {
            int nb = n0 + nt * 8;
            unsigned b0 = __float_as_uint(Bs[(kb + t) * 258 + nb + g]);
            unsigned b1 = __float_as_uint(Bs[(kb + t + 4) * 258 + nb + g]);
#pragma unroll
            for (int mi = 0; mi < 4; ++mi)
                mma8(acc[mi][nt], aF[mi][0], aF[mi][1], aF[mi][2], aF[mi][3], b0, b1);
        }
    }
    const float SCALE = 0.17677669529663687f; // 32^-0.5
#pragma unroll
    for (int mi = 0; mi < 4; ++mi)
#pragma unroll
        for (int nt = 0; nt < 4; ++nt) {
            int lr = mi * 16 + g;
            int pc = ph * 256 + n0 + nt * 8 + 2 * t;
            size_t base = (((size_t)(b * 16 + h)) * 64 + lr) * 512 + pc;
            *(float2*)&g_sim[base] =
                make_float2(acc[mi][nt][0] * SCALE, acc[mi][nt][1] * SCALE);
            *(float2*)&g_sim[base + (size_t)8 * 512] =
                make_float2(acc[mi][nt][2] * SCALE, acc[mi][nt][3] * SCALE);
        }
}

// ---------------- fused pairwise MLPs + softmax (FFMA2 packed) ----------------
#define SM4_FLOATS (512 * 33 + 2048 + 2048 + 256 + 1024 + 64 + 16 + 32)
__global__ void __launch_bounds__(512) pair_kernel(
    const float* __restrict__ xp, const float* __restrict__ xl,
    const float* __restrict__ w_mlp1, const float* __restrict__ w_mlp2,
    const float* __restrict__ b_mlp2, const float* __restrict__ sigma,
    const float* __restrict__ w_pe1, const float* __restrict__ b_pe1,
    const float* __restrict__ w_pe2, const float* __restrict__ b_pe2)
{
    extern __shared__ float sm[];
    float* lg    = sm;                 // 512*33 logits (padded)
    float* w1t   = lg + 512 * 33;      // [k][i] transposed w_mlp1, 64*32
    float* w2s   = w1t + 2048;         // w_mlp2 as-is, 64*32
    float* wpe1t = w2s + 2048;         // [k][i(pad4)], 64*4
    float* wpe2s = wpe1t + 256;        // w_pe2 as-is, 64*16
    float* bpe1s = wpe2s + 1024;       // 64
    float* bpe2s = bpe1s + 64;         // 16
    float* bm2s  = bpe2s + 16;         // 32

    const int tid = threadIdx.x;
    const int l = blockIdx.x, b = blockIdx.y;

    for (int e = tid; e < 2048; e += 512) { int i = e >> 6, k = e & 63; w1t[k * 32 + i] = w_mlp1[e]; }
    for (int e = tid; e < 2048; e += 512) w2s[e] = w_mlp2[e];
    if (tid < 192) { int i = tid >> 6, k = tid & 63; wpe1t[k * 4 + i] = w_pe1[tid]; }
    for (int e = tid; e < 1024; e += 512) wpe2s[e] = w_pe2[e];
    if (tid < 64) bpe1s[tid] = b_pe1[tid];
    if (tid < 16) bpe2s[tid] = b_pe2[tid];
    if (tid < 32) bm2s[tid]  = b_mlp2[tid];
    __syncthreads();

    const int p = tid;
    const float sg = sigma[0];
    const float cpe = -0.5f / (sg * sg);
    const int rowc = b * 512 + p, rowl = b * 64 + l;
    float d0 = xp[rowc * 3 + 0] - xl[rowl * 3 + 0];
    float d1 = xp[rowc * 3 + 1] - xl[rowl * 3 + 1];
    float d2 = xp[rowc * 3 + 2] - xl[rowl * 3 + 2];
    float pe0 = __expf(cpe * d0), pe1v = __expf(cpe * d1), pe2v = __expf(cpe * d2);

    // s pairs: sp[0..7] = sim heads, sp[8..15] = dis_emb
    u64 sp[16];
    {
        size_t base = (((size_t)b * 16) * 64 + l) * 512 + p;
#pragma unroll
        for (int h2 = 0; h2 < 8; ++h2) {
            float s0 = g_sim[base + (size_t)(2 * h2) * 64 * 512];
            float s1 = g_sim[base + (size_t)(2 * h2 + 1) * 64 * 512];
            sp[h2] = pk2(s0, s1);
        }
    }

    // positional-encoding MLP: 3 -> 64 (mish) -> 16, packed accumulation
    u64 de2[8];
#pragma unroll
    for (int j = 0; j < 8; ++j) de2[j] = pk2(bpe2s[2 * j], bpe2s[2 * j + 1]);
#pragma unroll 4
    for (int k = 0; k < 64; ++k) {
        float hk = bpe1s[k] + pe0 * wpe1t[k * 4] + pe1v * wpe1t[k * 4 + 1] + pe2v * wpe1t[k * 4 + 2];
        float m = mishf(hk);
        u64 m2 = pk2(m, m);
        const ulonglong2* wr = (const ulonglong2*)(wpe2s + k * 16);
#pragma unroll
        for (int q = 0; q < 4; ++q) {
            ulonglong2 w = wr[q];
            de2[2 * q + 0] = ffma2(m2, w.x, de2[2 * q + 0]);
            de2[2 * q + 1] = ffma2(m2, w.y, de2[2 * q + 1]);
        }
    }
#pragma unroll
    for (int j = 0; j < 8; ++j) sp[8 + j] = de2[j];

    // attention MLP: 32 -> 64 (mish) -> 32, packed
    u64 o2[16];
#pragma unroll
    for (int j = 0; j < 16; ++j) o2[j] = pk2(bm2s[2 * j], bm2s[2 * j + 1]);
    const u64 z2 = pk2(0.f, 0.f);
#pragma unroll 2
    for (int k = 0; k < 64; ++k) {
        const ulonglong2* w1r = (const ulonglong2*)(w1t + k * 32);
        u64 h2 = z2;
#pragma unroll
        for (int q = 0; q < 8; ++q) {
            ulonglong2 w = w1r[q];
            h2 = ffma2(sp[2 * q + 0], w.x, h2);
            h2 = ffma2(sp[2 * q + 1], w.y, h2);
        }
        float2 hh = up2(h2);
        float m = mishf(hh.x + hh.y);
        u64 m2 = pk2(m, m);
        const ulonglong2* w2r = (const ulonglong2*)(w2s + k * 32);
#pragma unroll
        for (int q = 0; q < 8; ++q) {
            ulonglong2 w = w2r[q];
            o2[2 * q + 0] = ffma2(m2, w.x, o2[2 * q + 0]);
            o2[2 * q + 1] = ffma2(m2, w.y, o2[2 * q + 1]);
        }
    }
#pragma unroll
    for (int j = 0; j < 16; ++j) {
        float2 v = up2(o2[j]);
        lg[p * 33 + 2 * j + 0] = v.x;
        lg[p * 33 + 2 * j + 1] = v.y;
    }
    __syncthreads();

    // softmax over p per channel; warp w handles channels 2w, 2w+1
    const int w = tid >> 5, lane = tid & 31;
#pragma unroll
    for (int cc = 0; cc < 2; ++cc) {
        int c = w * 2 + cc;
        float mx = -3.4e38f;
#pragma unroll
        for (int i = 0; i < 16; ++i) mx = fmaxf(mx, lg[(lane + i * 32) * 33 + c]);
#pragma unroll
        for (int off = 16; off; off >>= 1) mx = fmaxf(mx, __shfl_xor_sync(0xffffffffu, mx, off));
        float ev[16]; float sum = 0.f;
#pragma unroll
        for (int i = 0; i < 16; ++i) {
            ev[i] = __expf(lg[(lane + i * 32) * 33 + c] - mx);
            sum += ev[i];
        }
#pragma unroll
        for (int off = 16; off; off >>= 1) sum += __shfl_xor_sync(0xffffffffu, sum, off);
        float inv = 1.0f / sum;
        size_t base = (((size_t)b * 32 + c) * 64 + l) * 512;
#pragma unroll
        for (int i = 0; i < 16; ++i) g_probs[base + lane + i * 32] = ev[i] * inv;
    }
}

// ---------------- out_pre[b,l,h,d] = sum_p probs[b,h,l,p] * cv[b,p,h,d] --------
__global__ void __launch_bounds__(256) outagg_kernel()
{
    const int b = blockIdx.x, h = blockIdx.y;
    __shared__ float Acs[64][128];
    __shared__ float Bcs[128][32];
    const int tid = threadIdx.x;
    const int d = tid & 31, lgp = tid >> 5, l0 = lgp * 8;
    float acc[8];
#pragma unroll
    for (int j = 0; j < 8; ++j) acc[j] = 0.f;

    for (int pc = 0; pc < 512; pc += 128) {
        __syncthreads();
        for (int e = tid; e < 2048; e += 256) {
            int l = e >> 5, pq = (e & 31) * 4;
            *(float4*)&Acs[l][pq] =
                *(const float4*)&g_probs[(((size_t)b * 32 + h) * 64 + l) * 512 + pc + pq];
        }
        for (int e = tid; e < 1024; e += 256) {
            int p = e >> 3, d4 = (e & 7) * 4;
            *(float4*)&Bcs[p][d4] =
                *(const float4*)&g_cv[((size_t)(b * 512 + pc + p)) * 512 + h * 32 + d4];
        }
        __syncthreads();
        for (int p = 0; p < 128; p += 4) {
            float bv0 = Bcs[p][d], bv1 = Bcs[p + 1][d], bv2 = Bcs[p + 2][d], bv3 = Bcs[p + 3][d];
#pragma unroll
            for (int j = 0; j < 8; ++j) {
                float4 a = *(const float4*)&Acs[l0 + j][p];
                acc[j] += a.x * bv0 + a.y * bv1 + a.z * bv2 + a.w * bv3;
            }
        }
    }
#pragma unroll
    for (int j = 0; j < 8; ++j)
        g_outpre[((size_t)(b * 64 + l0 + j)) * 512 + h * 32 + d] = acc[j];
}

// ---------------- distance path: aggregate + tiny MLP -------------------------
__global__ void __launch_bounds__(256) disagg_kernel(
    const float* __restrict__ xp, const float* __restrict__ xl,
    const float* __restrict__ w_dis1, const float* __restrict__ b_dis1,
    const float* __restrict__ w_dis2, const float* __restrict__ b_dis2,
    float* __restrict__ out)
{
    const int l = blockIdx.x, b = blockIdx.y;
    __shared__ float xps[512 * 3];
    __shared__ float ods[3][16];
    __shared__ float zs[3][32];
    const int tid = threadIdx.x;
    for (int e = tid; e < 1536; e += 256) xps[e] = xp[(size_t)b * 1536 + e];
    __syncthreads();

    const int w = tid >> 5, lane = tid & 31;
#pragma unroll
    for (int q = 0; q < 6; ++q) {
        int idx = w * 6 + q;
        int i = idx >> 4, h = idx & 15;
        size_t base = (((size_t)b * 32 + 16 + h) * 64 + l) * 512;
        float sum = 0.f;
#pragma unroll
        for (int it = 0; it < 16; ++it) {
            int p = lane + it * 32;
            sum += g_probs[base + p] * xps[p * 3 + i];
        }
#pragma unroll
        for (int off = 16; off; off >>= 1) sum += __shfl_xor_sync(0xffffffffu, sum, off);
        if (lane == 0) ods[i][h] = sum - xl[(size_t)(b * 64 + l) * 3 + i];
    }
    __syncthreads();
    if (tid < 96) {
        int i = tid >> 5, k = tid & 31;
        float hz = b_dis1[k];
#pragma unroll
        for (int j = 0; j < 16; ++j) hz += ods[i][j] * w_dis1[j * 32 + k];
        zs[i][k] = mishf(hz);
    }
    __syncthreads();
    if (tid < 48) {
        int i = tid / 16, h = tid % 16;
        float y = b_dis2[h];
#pragma unroll
        for (int k = 0; k < 32; ++k) y += zs[i][k] * w_dis2[k * 16 + h];
        out[OUT0 + (((size_t)b * 64 + l) * 3 + i) * 16 + h] = y;
    }
}

// ---------------- launch -------------------------------------------------------
extern "C" void kernel_launch(void* const* d_in, const int* in_sizes, int n_in,
                              void* d_out, int out_size)
{
    (void)in_sizes; (void)n_in; (void)out_size;
    const float* h_ligand = (const float*)d_in[0];
    const float* context  = (const float*)d_in[1];
    const float* xp       = (const float*)d_in[2];
    const float* xl       = (const float*)d_in[3];
    const float* w_qk     = (const float*)d_in[4];
    // d_in[5] = w_v (unused by the reference)
    const float* w_cqk    = (const float*)d_in[6];
    const float* w_cv     = (const float*)d_in[7];
    const float* w_mlp1   = (const float*)d_in[8];
    const float* w_mlp2   = (const float*)d_in[9];
    const float* b_mlp2   = (const float*)d_in[10];
    const float* w_out    = (const float*)d_in[11];
    const float* b_out    = (const float*)d_in[12];
    const float* w_dis1   = (const float*)d_in[13];
    const float* b_dis1   = (const float*)d_in[14];
    const float* w_dis2   = (const float*)d_in[15];
    const float* b_dis2   = (const float*)d_in[16];
    const float* sigma    = (const float*)d_in[17];
    const float* w_pe1    = (const float*)d_in[18];
    const float* b_pe1    = (const float*)d_in[19];
    const float* w_pe2    = (const float*)d_in[20];
    const float* b_pe2    = (const float*)d_in[21];
    float* out = (float*)d_out;

    void *p_qk, *p_cqk, *p_cv, *p_outpre;
    cudaGetSymbolAddress(&p_qk, g_qk);
    cudaGetSymbolAddress(&p_cqk, g_cqk);
    cudaGetSymbolAddress(&p_cv, g_cv);
    cudaGetSymbolAddress(&p_outpre, g_outpre);

    // #1 qk projection (tf32)
    tgemm_k<0><<<dim3(4, 8), 256>>>(h_ligand, w_qk, nullptr,
                                    (float*)p_qk, nullptr, 1024, 512, 128);
    // #2 cqk + cv projections fused in one launch (shared A = context)
    tgemm_k<1><<<dim3(8, 64), 256>>>(context, w_cqk, w_cv,
                                     (float*)p_cqk, (float*)p_cv, 8192, 512, 256);
    // #3 similarity scores (tf32 mma)
    sim_mma_kernel<<<dim3(2, 16, 16), 256>>>();

    // #4 fused pairwise MLPs + softmax  (profiled slot)
    const int sm4_bytes = SM4_FLOATS * (int)sizeof(float);
    cudaFuncSetAttribute(pair_kernel, cudaFuncAttributeMaxDynamicSharedMemorySize, sm4_bytes);
    pair_kernel<<<dim3(64, 16), 512, sm4_bytes>>>(xp, xl, w_mlp1, w_mlp2, b_mlp2,
                                                  sigma, w_pe1, b_pe1, w_pe2, b_pe2);

    // #5 context path: attn @ cv
    outagg_kernel<<<dim3(16, 16), 256>>>();
    // #6 out-proj (+bias, fp32) into d_out
    sgemm_k<1><<<dim3(1, 8), 256>>>((const float*)p_outpre, w_out, b_out, out, 1024, 128, 512);
    // #7 distance path into d_out
    disagg_kernel<<<dim3(64, 16), 256>>>(xp, xl, w_dis1, b_dis1, w_dis2, b_dis2, out);
}

// round 5
// speedup vs baseline: 1.1976x; 1.0238x over previous
#include <cuda_runtime.h>
#include <cstddef>

#define OUT0 131072 // 1024*128, offset of out_dis in d_out

typedef unsigned long long u64;

// ---------------- scratch (device globals; no allocation allowed) -------------
__device__ float g_qk[1024 * 512];            // [B*L][INNER]
__device__ float g_cqk[8192 * 512];           // [B*P][INNER]
__device__ float g_cv[8192 * 512];            // [B*P][INNER]
__device__ float g_sim[16 * 16 * 64 * 512];   // [b][h][l][p] (scaled)
__device__ float g_probs[16 * 32 * 64 * 512]; // [b][c][l][p]
__device__ float g_outpre[1024 * 512];        // [B*L][INNER]

// mish(x) = x*tanh(softplus(x)) = x * u/(u+2), u = e^x*(e^x+2)  (exact identity)
__device__ __forceinline__ float mishf(float x) {
    float t = __expf(fminf(x, 8.0f));
    float u = t * (t + 2.0f);
    return x * __fdividef(u, u + 2.0f);
}

__device__ __forceinline__ float tf32r(float x) {
    unsigned u;
    asm("cvt.rna.tf32.f32 %0, %1;" : "=r"(u) : "f"(x));
    return __uint_as_float(u);
}

__device__ __forceinline__ void mma8(float* c, unsigned a0, unsigned a1,
                                     unsigned a2, unsigned a3,
                                     unsigned b0, unsigned b1) {
    asm volatile(
        "mma.sync.aligned.m16n8k8.row.col.f32.tf32.tf32.f32 "
        "{%0,%1,%2,%3},{%4,%5,%6,%7},{%8,%9},{%0,%1,%2,%3};"
        : "+f"(c[0]), "+f"(c[1]), "+f"(c[2]), "+f"(c[3])
        : "r"(a0), "r"(a1), "r"(a2), "r"(a3), "r"(b0), "r"(b1));
}

// ---- packed f32x2 helpers (Blackwell FFMA2 — only reachable via PTX) ---------
__device__ __forceinline__ u64 ffma2(u64 a, u64 b, u64 c) {
    u64 d;
    asm("fma.rn.f32x2 %0, %1, %2, %3;" : "=l"(d) : "l"(a), "l"(b), "l"(c));
    return d;
}
__device__ __forceinline__ u64 pk2(float x, float y) {
    u64 r;
    asm("mov.b64 %0, {%1, %2};" : "=l"(r) : "f"(x), "f"(y));
    return r;
}
__device__ __forceinline__ float2 up2(u64 v) {
    float2 r;
    asm("mov.b64 {%0, %1}, %2;" : "=f"(r.x), "=f"(r.y) : "l"(v));
    return r;
}

// ---------------- tf32 tensor-core GEMM: C[M,N] = A[M,K] @ B[K,N] -------------
// DUAL=1: N logically 1024 split across two 512-wide weight/output pairs.
template <int DUAL>
__global__ void __launch_bounds__(256) tgemm_k(
    const float* __restrict__ A, const float* __restrict__ B0,
    const float* __restrict__ B1, float* __restrict__ C0,
    float* __restrict__ C1, int M, int N, int K)
{
    __shared__ float As[128][36];
    __shared__ float Bs[32][136];
    const int tid = threadIdx.x;
    const int lane = tid & 31, warp = tid >> 5;
    const int wm = warp >> 1, wn = warp & 1;
    const int g = lane >> 2, t = lane & 3;
    const int row0 = blockIdx.y * 128;
    int col0 = blockIdx.x * 128;
    const float* Bm = B0;
    float* C = C0;
    if (DUAL && col0 >= 512) { Bm = B1; C = C1; col0 -= 512; }

    float acc[2][8][4];
#pragma unroll
    for (int mt = 0; mt < 2; ++mt)
#pragma unroll
        for (int nt = 0; nt < 8; ++nt)
#pragma unroll
            for (int q = 0; q < 4; ++q) acc[mt][nt][q] = 0.f;

    for (int k0 = 0; k0 < K; k0 += 32) {
        float4 va[4], vb[4];
#pragma unroll
        for (int i = 0; i < 4; ++i) {
            int f4 = tid + i * 256;
            int r = f4 >> 3, kc = (f4 & 7) * 4;
            va[i] = *(const float4*)&A[(size_t)(row0 + r) * K + k0 + kc];
            int kk = f4 >> 5, nc = (f4 & 31) * 4;
            vb[i] = *(const float4*)&Bm[(size_t)(k0 + kk) * N + col0 + nc];
        }
        __syncthreads();
#pragma unroll
        for (int i = 0; i < 4; ++i) {
            int f4 = tid + i * 256;
            int r = f4 >> 3, kc = (f4 & 7) * 4;
            As[r][kc + 0] = tf32r(va[i].x);
            As[r][kc + 1] = tf32r(va[i].y);
            As[r][kc + 2] = tf32r(va[i].z);
            As[r][kc + 3] = tf32r(va[i].w);
            int kk = f4 >> 5, nc = (f4 & 31) * 4;
            Bs[kk][nc + 0] = tf32r(vb[i].x);
            Bs[kk][nc + 1] = tf32r(vb[i].y);
            Bs[kk][nc + 2] = tf32r(vb[i].z);
            Bs[kk][nc + 3] = tf32r(vb[i].w);
        }
        __syncthreads();
#pragma unroll
        for (int ks = 0; ks < 4; ++ks) {
            const int kb = ks * 8;
            unsigned a[2][4];
#pragma unroll
            for (int mt = 0; mt < 2; ++mt) {
                int rb = wm * 32 + mt * 16;
                a[mt][0] = __float_as_uint(As[rb + g][kb + t]);
                a[mt][1] = __float_as_uint(As[rb + g + 8][kb + t]);
                a[mt][2] = __float_as_uint(As[rb + g][kb + t + 4]);
                a[mt][3] = __float_as_uint(As[rb + g + 8][kb + t + 4]);
            }
#pragma unroll
            for (int nt = 0; nt < 8; ++nt) {
                int nb = wn * 64 + nt * 8;
                unsigned b0 = __float_as_uint(Bs[kb + t][nb + g]);
                unsigned b1 = __float_as_uint(Bs[kb + t + 4][nb + g]);
#pragma unroll
                for (int mt = 0; mt < 2; ++mt)
                    mma8(acc[mt][nt], a[mt][0], a[mt][1], a[mt][2], a[mt][3], b0, b1);
            }
        }
    }
#pragma unroll
    for (int mt = 0; mt < 2; ++mt) {
#pragma unroll
        for (int nt = 0; nt < 8; ++nt) {
            int r = row0 + wm * 32 + mt * 16 + g;
            int c = col0 + wn * 64 + nt * 8 + 2 * t;
            *(float2*)&C[(size_t)r * N + c] = make_float2(acc[mt][nt][0], acc[mt][nt][1]);
            *(float2*)&C[(size_t)(r + 8) * N + c] = make_float2(acc[mt][nt][2], acc[mt][nt][3]);
        }
    }
}

// ---------------- fp32 SIMT SGEMM (final out-proj, +bias) ---------------------
template <int BIAS>
__global__ void __launch_bounds__(256) sgemm_k(
    const float* __restrict__ A, const float* __restrict__ B,
    const float* __restrict__ bias, float* __restrict__ C,
    int M, int N, int K)
{
    __shared__ float As[8][128];
    __shared__ float Bs[8][128];
    const int t  = threadIdx.x;
    const int tx = t & 15, ty = t >> 4;
    const int row0 = blockIdx.y * 128, col0 = blockIdx.x * 128;

    float acc[8][8];
#pragma unroll
    for (int i = 0; i < 8; ++i)
#pragma unroll
        for (int j = 0; j < 8; ++j) acc[i][j] = 0.f;

    const int aRow = t >> 1, aCol = (t & 1) * 4;
    const int bRow = t >> 5, bCol = (t & 31) * 4;
    const float* Aptr = A + (size_t)(row0 + aRow) * K + aCol;
    const float* Bptr = B + (size_t)bRow * N + col0 + bCol;

    for (int k0 = 0; k0 < K; k0 += 8) {
        float4 av = *(const float4*)(Aptr + k0);
        float4 bv = *(const float4*)(Bptr + (size_t)k0 * N);
        __syncthreads();
        As[aCol + 0][aRow] = av.x;
        As[aCol + 1][aRow] = av.y;
        As[aCol + 2][aRow] = av.z;
        As[aCol + 3][aRow] = av.w;
        *(float4*)&Bs[bRow][bCol] = bv;
        __syncthreads();
#pragma unroll
        for (int kk = 0; kk < 8; ++kk) {
            float a[8], bb[8];
            *(float4*)&a[0]  = *(const float4*)&As[kk][ty * 8];
            *(float4*)&a[4]  = *(const float4*)&As[kk][ty * 8 + 4];
            *(float4*)&bb[0] = *(const float4*)&Bs[kk][tx * 8];
            *(float4*)&bb[4] = *(const float4*)&Bs[kk][tx * 8 + 4];
#pragma unroll
            for (int i = 0; i < 8; ++i)
#pragma unroll
                for (int j = 0; j < 8; ++j) acc[i][j] += a[i] * bb[j];
        }
    }
#pragma unroll
    for (int i = 0; i < 8; ++i) {
        int r = row0 + ty * 8 + i;
#pragma unroll
        for (int j4 = 0; j4 < 2; ++j4) {
            int c = col0 + tx * 8 + j4 * 4;
            float4 v;
            v.x = acc[i][j4 * 4 + 0];
            v.y = acc[i][j4 * 4 + 1];
            v.z = acc[i][j4 * 4 + 2];
            v.w = acc[i][j4 * 4 + 3];
            if (BIAS) {
                v.x += bias[c + 0]; v.y += bias[c + 1];
                v.z += bias[c + 2]; v.w += bias[c + 3];
            }
            *(float4*)&C[(size_t)r * N + c] = v;
        }
    }
}

// ---------------- sim via tf32 mma: per (p-half, h, b) 64x256x32 --------------
__global__ void __launch_bounds__(256) sim_mma_kernel()
{
    __shared__ float As[64 * 34];   // [l][d]
    __shared__ float Bs[32 * 258];  // [d][p] (transposed)
    const int ph = blockIdx.x, h = blockIdx.y, b = blockIdx.z;
    const int tid = threadIdx.x;
    const int w = tid >> 5, lane = tid & 31, g = lane >> 2, t = lane & 3;

    for (int e = tid; e < 2048; e += 256) {
        int lr = e >> 5, d = e & 31;
        As[lr * 34 + d] = tf32r(g_qk[((size_t)(b * 64 + lr)) * 512 + h * 32 + d]);
    }
    for (int e = tid; e < 8192; e += 256) {
        int p = e >> 5, d = e & 31;
        Bs[d * 258 + p] = tf32r(g_cqk[((size_t)(b * 512 + ph * 256 + p)) * 512 + h * 32 + d]);
    }
    __syncthreads();

    float acc[4][4][4];
#pragma unroll
    for (int mi = 0; mi < 4; ++mi)
#pragma unroll
        for (int nt = 0; nt < 4; ++nt)
#pragma unroll
            for (int q = 0; q < 4; ++q) acc[mi][nt][q] = 0.f;

    const int n0 = w * 32;
#pragma unroll
    for (int kt = 0; kt < 4; ++kt) {
        const int kb = kt * 8;
        unsigned aF[4][4];
#pragma unroll
        for (int mi = 0; mi < 4; ++mi) {
            int rA = mi * 16;
            aF[mi][0] = __float_as_uint(As[(rA + g) * 34 + kb + t]);
            aF[mi][1] = __float_as_uint(As[(rA + g + 8) * 34 + kb + t]);
            aF[mi][2] = __float_as_uint(As[(rA + g) * 34 + kb + t + 4]);
            aF[mi][3] = __float_as_uint(As[(rA + g + 8) * 34 + kb + t + 4]);
        }
#pragma unroll
        for (int nt = 0; nt < 4; ++nt) {
            int nb = n0 + nt * 8;
            unsigned b0 = __float_as_uint(Bs[(kb + t) * 258 + nb + g]);
            unsigned b1 = __float_as_uint(Bs[(kb + t + 4) * 258 + nb + g]);
#pragma unroll
            for (int mi = 0; mi < 4; ++mi)
                mma8(acc[mi][nt], aF[mi][0], aF[mi][1], aF[mi][2], aF[mi][3], b0, b1);
        }
    }
    const float SCALE = 0.17677669529663687f; // 32^-0.5
#pragma unroll
    for (int mi = 0; mi < 4; ++mi)
#pragma unroll
        for (int nt = 0; nt < 4; ++nt) {
            int lr = mi * 16 + g;
            int pc = ph * 256 + n0 + nt * 8 + 2 * t;
            size_t base = (((size_t)(b * 16 + h)) * 64 + lr) * 512 + pc;
            *(float2*)&g_sim[base] =
                make_float2(acc[mi][nt][0] * SCALE, acc[mi][nt][1] * SCALE);
            *(float2*)&g_sim[base + (size_t)8 * 512] =
                make_float2(acc[mi][nt][2] * SCALE, acc[mi][nt][3] * SCALE);
        }
}

// ---------------- fused pairwise MLPs + softmax (FFMA2, 2 p per thread) -------
#define SM4_FLOATS (512 * 33 + 2048 + 2048 + 256 + 1024 + 64 + 16 + 32)
__global__ void __launch_bounds__(256) pair_kernel(
    const float* __restrict__ xp, const float* __restrict__ xl,
    const float* __restrict__ w_mlp1, const float* __restrict__ w_mlp2,
    const float* __restrict__ b_mlp2, const float* __restrict__ sigma,
    const float* __restrict__ w_pe1, const float* __restrict__ b_pe1,
    const float* __restrict__ w_pe2, const float* __restrict__ b_pe2)
{
    extern __shared__ float sm[];
    float* lg    = sm;                 // 512*33 logits (padded)
    float* w1t   = lg + 512 * 33;      // [k][i] transposed w_mlp1, 64*32
    float* w2s   = w1t + 2048;         // w_mlp2 as-is, 64*32
    float* wpe1t = w2s + 2048;         // [k][i(pad4)], 64*4
    float* wpe2s = wpe1t + 256;        // w_pe2 as-is, 64*16
    float* bpe1s = wpe2s + 1024;       // 64
    float* bpe2s = bpe1s + 64;         // 16
    float* bm2s  = bpe2s + 16;         // 32

    const int tid = threadIdx.x;
    const int l = blockIdx.x, b = blockIdx.y;

    for (int e = tid; e < 2048; e += 256) { int i = e >> 6, k = e & 63; w1t[k * 32 + i] = w_mlp1[e]; }
    for (int e = tid; e < 2048; e += 256) w2s[e] = w_mlp2[e];
    if (tid < 192) { int i = tid >> 6, k = tid & 63; wpe1t[k * 4 + i] = w_pe1[tid]; }
    for (int e = tid; e < 1024; e += 256) wpe2s[e] = w_pe2[e];
    if (tid < 64) bpe1s[tid] = b_pe1[tid];
    if (tid < 16) bpe2s[tid] = b_pe2[tid];
    if (tid < 32) bm2s[tid]  = b_mlp2[tid];
    __syncthreads();

    const float sg = sigma[0];
    const float cpe = -0.5f / (sg * sg);
    const int rowl = b * 64 + l;
    const float xl0 = xl[rowl * 3 + 0], xl1 = xl[rowl * 3 + 1], xl2 = xl[rowl * 3 + 2];

    const int p0 = tid, p1 = tid + 256;
    const float* xpr0 = xp + (size_t)(b * 512 + p0) * 3;
    const float* xpr1 = xp + (size_t)(b * 512 + p1) * 3;
    float peA0 = __expf(cpe * (xpr0[0] - xl0));
    float peA1 = __expf(cpe * (xpr0[1] - xl1));
    float peA2 = __expf(cpe * (xpr0[2] - xl2));
    float peB0 = __expf(cpe * (xpr1[0] - xl0));
    float peB1 = __expf(cpe * (xpr1[1] - xl1));
    float peB2 = __expf(cpe * (xpr1[2] - xl2));

    // s pairs for both p: [0..7] sim heads, [8..15] dis_emb
    u64 sp0[16], sp1[16];
    {
        size_t base = (((size_t)b * 16) * 64 + l) * 512;
#pragma unroll
        for (int h2 = 0; h2 < 8; ++h2) {
            size_t o0 = base + (size_t)(2 * h2) * 64 * 512;
            size_t o1 = base + (size_t)(2 * h2 + 1) * 64 * 512;
            sp0[h2] = pk2(g_sim[o0 + p0], g_sim[o1 + p0]);
            sp1[h2] = pk2(g_sim[o0 + p1], g_sim[o1 + p1]);
        }
    }

    // positional-encoding MLP: 3 -> 64 (mish) -> 16, both p share weight loads
    {
        u64 deA[8], deB[8];
#pragma unroll
        for (int j = 0; j < 8; ++j) {
            u64 bb = pk2(bpe2s[2 * j], bpe2s[2 * j + 1]);
            deA[j] = bb; deB[j] = bb;
        }
#pragma unroll 1
        for (int k = 0; k < 64; ++k) {
            float w0 = wpe1t[k * 4], w1 = wpe1t[k * 4 + 1], w2 = wpe1t[k * 4 + 2];
            float bk = bpe1s[k];
            float hA = bk + peA0 * w0 + peA1 * w1 + peA2 * w2;
            float hB = bk + peB0 * w0 + peB1 * w1 + peB2 * w2;
            float mA = mishf(hA), mB = mishf(hB);
            u64 mA2 = pk2(mA, mA), mB2 = pk2(mB, mB);
            const ulonglong2* wr = (const ulonglong2*)(wpe2s + k * 16);
#pragma unroll
            for (int q = 0; q < 4; ++q) {
                ulonglong2 w = wr[q];
                deA[2 * q + 0] = ffma2(mA2, w.x, deA[2 * q + 0]);
                deA[2 * q + 1] = ffma2(mA2, w.y, deA[2 * q + 1]);
                deB[2 * q + 0] = ffma2(mB2, w.x, deB[2 * q + 0]);
                deB[2 * q + 1] = ffma2(mB2, w.y, deB[2 * q + 1]);
            }
        }
#pragma unroll
        for (int j = 0; j < 8; ++j) { sp0[8 + j] = deA[j]; sp1[8 + j] = deB[j]; }
    }

    // attention MLP: 32 -> 64 (mish) -> 32, both p share weight loads
    u64 oA[16], oB[16];
#pragma unroll
    for (int j = 0; j < 16; ++j) {
        u64 bb = pk2(bm2s[2 * j], bm2s[2 * j + 1]);
        oA[j] = bb; oB[j] = bb;
    }
    const u64 z2 = pk2(0.f, 0.f);
#pragma unroll 1
    for (int k = 0; k < 64; ++k) {
        const ulonglong2* w1r = (const ulonglong2*)(w1t + k * 32);
        u64 hA = z2, hB = z2;
#pragma unroll
        for (int q = 0; q < 8; ++q) {
            ulonglong2 w = w1r[q];
            hA = ffma2(sp0[2 * q + 0], w.x, hA);
            hA = ffma2(sp0[2 * q + 1], w.y, hA);
            hB = ffma2(sp1[2 * q + 0], w.x, hB);
            hB = ffma2(sp1[2 * q + 1], w.y, hB);
        }
        float2 aA = up2(hA), aB = up2(hB);
        float mA = mishf(aA.x + aA.y), mB = mishf(aB.x + aB.y);
        u64 mA2 = pk2(mA, mA), mB2 = pk2(mB, mB);
        const ulonglong2* w2r = (const ulonglong2*)(w2s + k * 32);
#pragma unroll
        for (int q = 0; q < 8; ++q) {
            ulonglong2 w = w2r[q];
            oA[2 * q + 0] = ffma2(mA2, w.x, oA[2 * q + 0]);
            oA[2 * q + 1] = ffma2(mA2, w.y, oA[2 * q + 1]);
            oB[2 * q + 0] = ffma2(mB2, w.x, oB[2 * q + 0]);
            oB[2 * q + 1] = ffma2(mB2, w.y, oB[2 * q + 1]);
        }
    }
#pragma unroll
    for (int j = 0; j < 16; ++j) {
        float2 vA = up2(oA[j]);
        float2 vB = up2(oB[j]);
        lg[p0 * 33 + 2 * j + 0] = vA.x;
        lg[p0 * 33 + 2 * j + 1] = vA.y;
        lg[p1 * 33 + 2 * j + 0] = vB.x;
        lg[p1 * 33 + 2 * j + 1] = vB.y;
    }
    __syncthreads();

    // softmax over p per channel; 8 warps, warp w handles channels 4w..4w+3
    const int w = tid >> 5, lane = tid & 31;
#pragma unroll
    for (int cc = 0; cc < 4; ++cc) {
        int c = w * 4 + cc;
        float mx = -3.4e38f;
#pragma unroll
        for (int i = 0; i < 16; ++i) mx = fmaxf(mx, lg[(lane + i * 32) * 33 + c]);
#pragma unroll
        for (int off = 16; off; off >>= 1) mx = fmaxf(mx, __shfl_xor_sync(0xffffffffu, mx, off));
        float ev[16]; float sum = 0.f;
#pragma unroll
        for (int i = 0; i < 16; ++i) {
            ev[i] = __expf(lg[(lane + i * 32) * 33 + c] - mx);
            sum += ev[i];
        }
#pragma unroll
        for (int off = 16; off; off >>= 1) sum += __shfl_xor_sync(0xffffffffu, sum, off);
        float inv = 1.0f / sum;
        size_t base = (((size_t)b * 32 + c) * 64 + l) * 512;
#pragma unroll
        for (int i = 0; i < 16; ++i) g_probs[base + lane + i * 32] = ev[i] * inv;
    }
}

// ---------------- out_pre[b,l,h,d] = sum_p probs[b,h,l,p] * cv[b,p,h,d] --------
__global__ void __launch_bounds__(256) outagg_kernel()
{
    const int b = blockIdx.x, h = blockIdx.y;
    __shared__ float Acs[64][128];
    __shared__ float Bcs[128][32];
    const int tid = threadIdx.x;
    const int d = tid & 31, lgp = tid >> 5, l0 = lgp * 8;
    float acc[8];
#pragma unroll
    for (int j = 0; j < 8; ++j) acc[j] = 0.f;

    for (int pc = 0; pc < 512; pc += 128) {
        __syncthreads();
        for (int e = tid; e < 2048; e += 256) {
            int l = e >> 5, pq = (e & 31) * 4;
            *(float4*)&Acs[l][pq] =
                *(const float4*)&g_probs[(((size_t)b * 32 + h) * 64 + l) * 512 + pc + pq];
        }
        for (int e = tid; e < 1024; e += 256) {
            int p = e >> 3, d4 = (e & 7) * 4;
            *(float4*)&Bcs[p][d4] =
                *(const float4*)&g_cv[((size_t)(b * 512 + pc + p)) * 512 + h * 32 + d4];
        }
        __syncthreads();
        for (int p = 0; p < 128; p += 4) {
            float bv0 = Bcs[p][d], bv1 = Bcs[p + 1][d], bv2 = Bcs[p + 2][d], bv3 = Bcs[p + 3][d];
#pragma unroll
            for (int j = 0; j < 8; ++j) {
                float4 a = *(const float4*)&Acs[l0 + j][p];
                acc[j] += a.x * bv0 + a.y * bv1 + a.z * bv2 + a.w * bv3;
            }
        }
    }
#pragma unroll
    for (int j = 0; j < 8; ++j)
        g_outpre[((size_t)(b * 64 + l0 + j)) * 512 + h * 32 + d] = acc[j];
}

// ---------------- distance path: aggregate + tiny MLP -------------------------
__global__ void __launch_bounds__(256) disagg_kernel(
    const float* __restrict__ xp, const float* __restrict__ xl,
    const float* __restrict__ w_dis1, const float* __restrict__ b_dis1,
    const float* __restrict__ w_dis2, const float* __restrict__ b_dis2,
    float* __restrict__ out)
{
    const int l = blockIdx.x, b = blockIdx.y;
    __shared__ float xps[512 * 3];
    __shared__ float ods[3][16];
    __shared__ float zs[3][32];
    const int tid = threadIdx.x;
    for (int e = tid; e < 1536; e += 256) xps[e] = xp[(size_t)b * 1536 + e];
    __syncthreads();

    const int w = tid >> 5, lane = tid & 31;
#pragma unroll
    for (int q = 0; q < 6; ++q) {
        int idx = w * 6 + q;
        int i = idx >> 4, h = idx & 15;
        size_t base = (((size_t)b * 32 + 16 + h) * 64 + l) * 512;
        float sum = 0.f;
#pragma unroll
        for (int it = 0; it < 16; ++it) {
            int p = lane + it * 32;
            sum += g_probs[base + p] * xps[p * 3 + i];
        }
#pragma unroll
        for (int off = 16; off; off >>= 1) sum += __shfl_xor_sync(0xffffffffu, sum, off);
        if (lane == 0) ods[i][h] = sum - xl[(size_t)(b * 64 + l) * 3 + i];
    }
    __syncthreads();
    if (tid < 96) {
        int i = tid >> 5, k = tid & 31;
        float hz = b_dis1[k];
#pragma unroll
        for (int j = 0; j < 16; ++j) hz += ods[i][j] * w_dis1[j * 32 + k];
        zs[i][k] = mishf(hz);
    }
    __syncthreads();
    if (tid < 48) {
        int i = tid / 16, h = tid % 16;
        float y = b_dis2[h];
#pragma unroll
        for (int k = 0; k < 32; ++k) y += zs[i][k] * w_dis2[k * 16 + h];
        out[OUT0 + (((size_t)b * 64 + l) * 3 + i) * 16 + h] = y;
    }
}

// ---------------- launch -------------------------------------------------------
extern "C" void kernel_launch(void* const* d_in, const int* in_sizes, int n_in,
                              void* d_out, int out_size)
{
    (void)in_sizes; (void)n_in; (void)out_size;
    const float* h_ligand = (const float*)d_in[0];
    const float* context  = (const float*)d_in[1];
    const float* xp       = (const float*)d_in[2];
    const float* xl       = (const float*)d_in[3];
    const float* w_qk     = (const float*)d_in[4];
    // d_in[5] = w_v (unused by the reference)
    const float* w_cqk    = (const float*)d_in[6];
    const float* w_cv     = (const float*)d_in[7];
    const float* w_mlp1   = (const float*)d_in[8];
    const float* w_mlp2   = (const float*)d_in[9];
    const float* b_mlp2   = (const float*)d_in[10];
    const float* w_out    = (const float*)d_in[11];
    const float* b_out    = (const float*)d_in[12];
    const float* w_dis1   = (const float*)d_in[13];
    const float* b_dis1   = (const float*)d_in[14];
    const float* w_dis2   = (const float*)d_in[15];
    const float* b_dis2   = (const float*)d_in[16];
    const float* sigma    = (const float*)d_in[17];
    const float* w_pe1    = (const float*)d_in[18];
    const float* b_pe1    = (const float*)d_in[19];
    const float* w_pe2    = (const float*)d_in[20];
    const float* b_pe2    = (const float*)d_in[21];
    float* out = (float*)d_out;

    void *p_qk, *p_cqk, *p_cv, *p_outpre;
    cudaGetSymbolAddress(&p_qk, g_qk);
    cudaGetSymbolAddress(&p_cqk, g_cqk);
    cudaGetSymbolAddress(&p_cv, g_cv);
    cudaGetSymbolAddress(&p_outpre, g_outpre);

    // #1 qk projection (tf32)
    tgemm_k<0><<<dim3(4, 8), 256>>>(h_ligand, w_qk, nullptr,
                                    (float*)p_qk, nullptr, 1024, 512, 128);
    // #2 cqk + cv projections fused in one launch (shared A = context)
    tgemm_k<1><<<dim3(8, 64), 256>>>(context, w_cqk, w_cv,
                                     (float*)p_cqk, (float*)p_cv, 8192, 512, 256);
    // #3 similarity scores (tf32 mma)
    sim_mma_kernel<<<dim3(2, 16, 16), 256>>>();

    // #4 fused pairwise MLPs + softmax  (profiled slot)
    const int sm4_bytes = SM4_FLOATS * (int)sizeof(float);
    cudaFuncSetAttribute(pair_kernel, cudaFuncAttributeMaxDynamicSharedMemorySize, sm4_bytes);
    pair_kernel<<<dim3(64, 16), 256, sm4_bytes>>>(xp, xl, w_mlp1, w_mlp2, b_mlp2,
                                                  sigma, w_pe1, b_pe1, w_pe2, b_pe2);

    // #5 context path: attn @ cv
    outagg_kernel<<<dim3(16, 16), 256>>>();
    // #6 out-proj (+bias, fp32) into d_out
    sgemm_k<1><<<dim3(1, 8), 256>>>((const float*)p_outpre, w_out, b_out, out, 1024, 128, 512);
    // #7 distance path into d_out
    disagg_kernel<<<dim3(64, 16), 256>>>(xp, xl, w_dis1, b_dis1, w_dis2, b_dis2, out);
}

// round 6
// speedup vs baseline: 1.2561x; 1.0488x over previous
#include <cuda_runtime.h>
#include <cstddef>

#define OUT0 131072 // 1024*128, offset of out_dis in d_out

typedef unsigned long long u64;

// ---------------- scratch (device globals; no allocation allowed) -------------
__device__ float g_qk[1024 * 512];            // [B*L][INNER]
__device__ float g_cqk[8192 * 512];           // [B*P][INNER]
__device__ float g_cv[8192 * 512];            // [B*P][INNER]
__device__ float g_sim[16 * 16 * 64 * 512];   // [b][h][l][p] (scaled)
__device__ float g_probs[16 * 32 * 64 * 512]; // [b][c][l][p]
__device__ float g_outpre[1024 * 512];        // [B*L][INNER]

// mish(x) = x*tanh(softplus(x)) = x * u/(u+2), u = e^x*(e^x+2)  (exact identity)
__device__ __forceinline__ float mishf(float x) {
    float t = __expf(fminf(x, 8.0f));
    float u = t * (t + 2.0f);
    return x * __fdividef(u, u + 2.0f);
}

__device__ __forceinline__ float tf32r(float x) {
    unsigned u;
    asm("cvt.rna.tf32.f32 %0, %1;" : "=r"(u) : "f"(x));
    return __uint_as_float(u);
}

__device__ __forceinline__ void mma8(float* c, unsigned a0, unsigned a1,
                                     unsigned a2, unsigned a3,
                                     unsigned b0, unsigned b1) {
    asm volatile(
        "mma.sync.aligned.m16n8k8.row.col.f32.tf32.tf32.f32 "
        "{%0,%1,%2,%3},{%4,%5,%6,%7},{%8,%9},{%0,%1,%2,%3};"
        : "+f"(c[0]), "+f"(c[1]), "+f"(c[2]), "+f"(c[3])
        : "r"(a0), "r"(a1), "r"(a2), "r"(a3), "r"(b0), "r"(b1));
}

// ---- packed f32x2 helpers (Blackwell FFMA2 — only reachable via PTX) ---------
__device__ __forceinline__ u64 ffma2(u64 a, u64 b, u64 c) {
    u64 d;
    asm("fma.rn.f32x2 %0, %1, %2, %3;" : "=l"(d) : "l"(a), "l"(b), "l"(c));
    return d;
}
__device__ __forceinline__ u64 pk2(float x, float y) {
    u64 r;
    asm("mov.b64 %0, {%1, %2};" : "=l"(r) : "f"(x), "f"(y));
    return r;
}
__device__ __forceinline__ float2 up2(u64 v) {
    float2 r;
    asm("mov.b64 {%0, %1}, %2;" : "=f"(r.x), "=f"(r.y) : "l"(v));
    return r;
}

// ---------------- tf32 tensor-core GEMM: C[M,N] = A[M,K] @ B[K,N] -------------
// DUAL=1: N logically 1024 split across two 512-wide weight/output pairs.
template <int DUAL>
__global__ void __launch_bounds__(256) tgemm_k(
    const float* __restrict__ A, const float* __restrict__ B0,
    const float* __restrict__ B1, float* __restrict__ C0,
    float* __restrict__ C1, int M, int N, int K)
{
    __shared__ float As[128][36];
    __shared__ float Bs[32][136];
    const int tid = threadIdx.x;
    const int lane = tid & 31, warp = tid >> 5;
    const int wm = warp >> 1, wn = warp & 1;
    const int g = lane >> 2, t = lane & 3;
    const int row0 = blockIdx.y * 128;
    int col0 = blockIdx.x * 128;
    const float* Bm = B0;
    float* C = C0;
    if (DUAL && col0 >= 512) { Bm = B1; C = C1; col0 -= 512; }

    float acc[2][8][4];
#pragma unroll
    for (int mt = 0; mt < 2; ++mt)
#pragma unroll
        for (int nt = 0; nt < 8; ++nt)
#pragma unroll
            for (int q = 0; q < 4; ++q) acc[mt][nt][q] = 0.f;

    for (int k0 = 0; k0 < K; k0 += 32) {
        float4 va[4], vb[4];
#pragma unroll
        for (int i = 0; i < 4; ++i) {
            int f4 = tid + i * 256;
            int r = f4 >> 3, kc = (f4 & 7) * 4;
            va[i] = *(const float4*)&A[(size_t)(row0 + r) * K + k0 + kc];
            int kk = f4 >> 5, nc = (f4 & 31) * 4;
            vb[i] = *(const float4*)&Bm[(size_t)(k0 + kk) * N + col0 + nc];
        }
        __syncthreads();
#pragma unroll
        for (int i = 0; i < 4; ++i) {
            int f4 = tid + i * 256;
            int r = f4 >> 3, kc = (f4 & 7) * 4;
            As[r][kc + 0] = tf32r(va[i].x);
            As[r][kc + 1] = tf32r(va[i].y);
            As[r][kc + 2] = tf32r(va[i].z);
            As[r][kc + 3] = tf32r(va[i].w);
            int kk = f4 >> 5, nc = (f4 & 31) * 4;
            Bs[kk][nc + 0] = tf32r(vb[i].x);
            Bs[kk][nc + 1] = tf32r(vb[i].y);
            Bs[kk][nc + 2] = tf32r(vb[i].z);
            Bs[kk][nc + 3] = tf32r(vb[i].w);
        }
        __syncthreads();
#pragma unroll
        for (int ks = 0; ks < 4; ++ks) {
            const int kb = ks * 8;
            unsigned a[2][4];
#pragma unroll
            for (int mt = 0; mt < 2; ++mt) {
                int rb = wm * 32 + mt * 16;
                a[mt][0] = __float_as_uint(As[rb + g][kb + t]);
                a[mt][1] = __float_as_uint(As[rb + g + 8][kb + t]);
                a[mt][2] = __float_as_uint(As[rb + g][kb + t + 4]);
                a[mt][3] = __float_as_uint(As[rb + g + 8][kb + t + 4]);
            }
#pragma unroll
            for (int nt = 0; nt < 8; ++nt) {
                int nb = wn * 64 + nt * 8;
                unsigned b0 = __float_as_uint(Bs[kb + t][nb + g]);
                unsigned b1 = __float_as_uint(Bs[kb + t + 4][nb + g]);
#pragma unroll
                for (int mt = 0; mt < 2; ++mt)
                    mma8(acc[mt][nt], a[mt][0], a[mt][1], a[mt][2], a[mt][3], b0, b1);
            }
        }
    }
#pragma unroll
    for (int mt = 0; mt < 2; ++mt) {
#pragma unroll
        for (int nt = 0; nt < 8; ++nt) {
            int r = row0 + wm * 32 + mt * 16 + g;
            int c = col0 + wn * 64 + nt * 8 + 2 * t;
            *(float2*)&C[(size_t)r * N + c] = make_float2(acc[mt][nt][0], acc[mt][nt][1]);
            *(float2*)&C[(size_t)(r + 8) * N + c] = make_float2(acc[mt][nt][2], acc[mt][nt][3]);
        }
    }
}

// ---------------- out-proj: out[r][c] = outpre[r] . w_out[:,c] + b[c] ---------
// block = 256 threads = 2 rows x 128 cols; grid = 512 blocks. K=512.
__global__ void __launch_bounds__(256) outproj_kernel(
    const float* __restrict__ A, const float* __restrict__ B,
    const float* __restrict__ bias, float* __restrict__ C)
{
    __shared__ float As[2][512];
    const int tid = threadIdx.x;
    const int r0 = blockIdx.x * 2;
    // load 2 A rows (1024 floats) with float4
    {
        const float4* src = (const float4*)&A[(size_t)r0 * 512];
        float4* dst = (float4*)&As[0][0];
        dst[tid] = src[tid];
    }
    __syncthreads();
    const int row = tid >> 7, c = tid & 127;
    const float* arow = As[row];
    float acc = bias[c];
    const float* bp = B + c;
#pragma unroll 8
    for (int k = 0; k < 512; k += 4) {
        float4 a = *(const float4*)&arow[k];
        acc += a.x * bp[(size_t)(k + 0) * 128];
        acc += a.y * bp[(size_t)(k + 1) * 128];
        acc += a.z * bp[(size_t)(k + 2) * 128];
        acc += a.w * bp[(size_t)(k + 3) * 128];
    }
    C[(size_t)(r0 + row) * 128 + c] = acc;
}

// ---------------- sim via tf32 mma: per (p-half, h, b) 64x256x32 --------------
__global__ void __launch_bounds__(256) sim_mma_kernel()
{
    __shared__ float As[64 * 34];   // [l][d]
    __shared__ float Bs[32 * 258];  // [d][p] (transposed)
    const int ph = blockIdx.x, h = blockIdx.y, b = blockIdx.z;
    const int tid = threadIdx.x;
    const int w = tid >> 5, lane = tid & 31, g = lane >> 2, t = lane & 3;

    for (int e = tid; e < 2048; e += 256) {
        int lr = e >> 5, d = e & 31;
        As[lr * 34 + d] = tf32r(g_qk[((size_t)(b * 64 + lr)) * 512 + h * 32 + d]);
    }
    for (int e = tid; e < 8192; e += 256) {
        int p = e >> 5, d = e & 31;
        Bs[d * 258 + p] = tf32r(g_cqk[((size_t)(b * 512 + ph * 256 + p)) * 512 + h * 32 + d]);
    }
    __syncthreads();

    float acc[4][4][4];
#pragma unroll
    for (int mi = 0; mi < 4; ++mi)
#pragma unroll
        for (int nt = 0; nt < 4; ++nt)
#pragma unroll
            for (int q = 0; q < 4; ++q) acc[mi][nt][q] = 0.f;

    const int n0 = w * 32;
#pragma unroll
    for (int kt = 0; kt < 4; ++kt) {
        const int kb = kt * 8;
        unsigned aF[4][4];
#pragma unroll
        for (int mi = 0; mi < 4; ++mi) {
            int rA = mi * 16;
            aF[mi][0] = __float_as_uint(As[(rA + g) * 34 + kb + t]);
            aF[mi][1] = __float_as_uint(As[(rA + g + 8) * 34 + kb + t]);
            aF[mi][2] = __float_as_uint(As[(rA + g) * 34 + kb + t + 4]);
            aF[mi][3] = __float_as_uint(As[(rA + g + 8) * 34 + kb + t + 4]);
        }
#pragma unroll
        for (int nt = 0; nt < 4; ++nt) {
            int nb = n0 + nt * 8;
            unsigned b0 = __float_as_uint(Bs[(kb + t) * 258 + nb + g]);
            unsigned b1 = __float_as_uint(Bs[(kb + t + 4) * 258 + nb + g]);
#pragma unroll
            for (int mi = 0; mi < 4; ++mi)
                mma8(acc[mi][nt], aF[mi][0], aF[mi][1], aF[mi][2], aF[mi][3], b0, b1);
        }
    }
    const float SCALE = 0.17677669529663687f; // 32^-0.5
#pragma unroll
    for (int mi = 0; mi < 4; ++mi)
#pragma unroll
        for (int nt = 0; nt < 4; ++nt) {
            int lr = mi * 16 + g;
            int pc = ph * 256 + n0 + nt * 8 + 2 * t;
            size_t base = (((size_t)(b * 16 + h)) * 64 + lr) * 512 + pc;
            *(float2*)&g_sim[base] =
                make_float2(acc[mi][nt][0] * SCALE, acc[mi][nt][1] * SCALE);
            *(float2*)&g_sim[base + (size_t)8 * 512] =
                make_float2(acc[mi][nt][2] * SCALE, acc[mi][nt][3] * SCALE);
        }
}

// ------- fused pairwise MLPs + softmax (FFMA2, 2 p/thread, 2-pass outputs) ----
#define SM4_FLOATS (512 * 33 + 2048 + 2048 + 256 + 1024 + 64 + 16 + 32)
__global__ void __launch_bounds__(256, 2) pair_kernel(
    const float* __restrict__ xp, const float* __restrict__ xl,
    const float* __restrict__ w_mlp1, const float* __restrict__ w_mlp2,
    const float* __restrict__ b_mlp2, const float* __restrict__ sigma,
    const float* __restrict__ w_pe1, const float* __restrict__ b_pe1,
    const float* __restrict__ w_pe2, const float* __restrict__ b_pe2)
{
    extern __shared__ float sm[];
    float* lg    = sm;                 // 512*33 logits (padded)
    float* w1t   = lg + 512 * 33;      // [k][i] transposed w_mlp1, 64*32
    float* w2s   = w1t + 2048;         // w_mlp2 as-is, 64*32
    float* wpe1t = w2s + 2048;         // [k][i(pad4)], 64*4
    float* wpe2s = wpe1t + 256;        // w_pe2 as-is, 64*16
    float* bpe1s = wpe2s + 1024;       // 64
    float* bpe2s = bpe1s + 64;         // 16
    float* bm2s  = bpe2s + 16;         // 32

    const int tid = threadIdx.x;
    const int l = blockIdx.x, b = blockIdx.y;

    for (int e = tid; e < 2048; e += 256) { int i = e >> 6, k = e & 63; w1t[k * 32 + i] = w_mlp1[e]; }
    for (int e = tid; e < 2048; e += 256) w2s[e] = w_mlp2[e];
    if (tid < 192) { int i = tid >> 6, k = tid & 63; wpe1t[k * 4 + i] = w_pe1[tid]; }
    for (int e = tid; e < 1024; e += 256) wpe2s[e] = w_pe2[e];
    if (tid < 64) bpe1s[tid] = b_pe1[tid];
    if (tid < 16) bpe2s[tid] = b_pe2[tid];
    if (tid < 32) bm2s[tid]  = b_mlp2[tid];
    __syncthreads();

    const float sg = sigma[0];
    const float cpe = -0.5f / (sg * sg);
    const int rowl = b * 64 + l;
    const float xl0 = xl[rowl * 3 + 0], xl1 = xl[rowl * 3 + 1], xl2 = xl[rowl * 3 + 2];

    const int p0 = tid, p1 = tid + 256;

    // s pairs for both p: [0..7] sim heads, [8..15] dis_emb
    u64 sp0[16], sp1[16];
    {
        size_t base = (((size_t)b * 16) * 64 + l) * 512;
#pragma unroll
        for (int h2 = 0; h2 < 8; ++h2) {
            size_t o0 = base + (size_t)(2 * h2) * 64 * 512;
            size_t o1 = base + (size_t)(2 * h2 + 1) * 64 * 512;
            sp0[h2] = pk2(g_sim[o0 + p0], g_sim[o1 + p0]);
            sp1[h2] = pk2(g_sim[o0 + p1], g_sim[o1 + p1]);
        }
    }

    // positional-encoding MLP: 3 -> 64 (mish) -> 16, both p share weight loads
    {
        const float* xpr0 = xp + (size_t)(b * 512 + p0) * 3;
        const float* xpr1 = xp + (size_t)(b * 512 + p1) * 3;
        float peA0 = __expf(cpe * (xpr0[0] - xl0));
        float peA1 = __expf(cpe * (xpr0[1] - xl1));
        float peA2 = __expf(cpe * (xpr0[2] - xl2));
        float peB0 = __expf(cpe * (xpr1[0] - xl0));
        float peB1 = __expf(cpe * (xpr1[1] - xl1));
        float peB2 = __expf(cpe * (xpr1[2] - xl2));

        u64 deA[8], deB[8];
#pragma unroll
        for (int j = 0; j < 8; ++j) {
            u64 bb = pk2(bpe2s[2 * j], bpe2s[2 * j + 1]);
            deA[j] = bb; deB[j] = bb;
        }
#pragma unroll 1
        for (int k = 0; k < 64; ++k) {
            float w0 = wpe1t[k * 4], w1 = wpe1t[k * 4 + 1], w2 = wpe1t[k * 4 + 2];
            float bk = bpe1s[k];
            float hA = bk + peA0 * w0 + peA1 * w1 + peA2 * w2;
            float hB = bk + peB0 * w0 + peB1 * w1 + peB2 * w2;
            float mA = mishf(hA), mB = mishf(hB);
            u64 mA2 = pk2(mA, mA), mB2 = pk2(mB, mB);
            const ulonglong2* wr = (const ulonglong2*)(wpe2s + k * 16);
#pragma unroll
            for (int q = 0; q < 4; ++q) {
                ulonglong2 w = wr[q];
                deA[2 * q + 0] = ffma2(mA2, w.x, deA[2 * q + 0]);
                deA[2 * q + 1] = ffma2(mA2, w.y, deA[2 * q + 1]);
                deB[2 * q + 0] = ffma2(mB2, w.x, deB[2 * q + 0]);
                deB[2 * q + 1] = ffma2(mB2, w.y, deB[2 * q + 1]);
            }
        }
#pragma unroll
        for (int j = 0; j < 8; ++j) { sp0[8 + j] = deA[j]; sp1[8 + j] = deB[j]; }
    }

    // attention MLP: 32 -> 64 (mish) -> 32, two passes of 16 output channels.
    // Hidden layer recomputed per pass; o-accumulators halved -> fits 128 regs.
    const u64 z2 = pk2(0.f, 0.f);
#pragma unroll 1
    for (int pass = 0; pass < 2; ++pass) {
        u64 oA[8], oB[8];
#pragma unroll
        for (int j = 0; j < 8; ++j) {
            u64 bb = pk2(bm2s[pass * 16 + 2 * j], bm2s[pass * 16 + 2 * j + 1]);
            oA[j] = bb; oB[j] = bb;
        }
#pragma unroll 1
        for (int k = 0; k < 64; ++k) {
            const ulonglong2* w1r = (const ulonglong2*)(w1t + k * 32);
            // 2 partial chains per point to break the 16-deep RAW chain
            u64 hA0 = z2, hA1 = z2, hB0 = z2, hB1 = z2;
#pragma unroll
            for (int q = 0; q < 4; ++q) {
                ulonglong2 w = w1r[q];
                hA0 = ffma2(sp0[2 * q + 0], w.x, hA0);
                hA0 = ffma2(sp0[2 * q + 1], w.y, hA0);
                hB0 = ffma2(sp1[2 * q + 0], w.x, hB0);
                hB0 = ffma2(sp1[2 * q + 1], w.y, hB0);
            }
#pragma unroll
            for (int q = 4; q < 8; ++q) {
                ulonglong2 w = w1r[q];
                hA1 = ffma2(sp0[2 * q + 0], w.x, hA1);
                hA1 = ffma2(sp0[2 * q + 1], w.y, hA1);
                hB1 = ffma2(sp1[2 * q + 0], w.x, hB1);
                hB1 = ffma2(sp1[2 * q + 1], w.y, hB1);
            }
            float2 a0 = up2(hA0), a1 = up2(hA1);
            float2 b0 = up2(hB0), b1 = up2(hB1);
            float mA = mishf((a0.x + a0.y) + (a1.x + a1.y));
            float mB = mishf((b0.x + b0.y) + (b1.x + b1.y));
            u64 mA2 = pk2(mA, mA), mB2 = pk2(mB, mB);
            const ulonglong2* w2r = (const ulonglong2*)(w2s + k * 32 + pass * 16);
#pragma unroll
            for (int q = 0; q < 4; ++q) {
                ulonglong2 w = w2r[q];
                oA[2 * q + 0] = ffma2(mA2, w.x, oA[2 * q + 0]);
                oA[2 * q + 1] = ffma2(mA2, w.y, oA[2 * q + 1]);
                oB[2 * q + 0] = ffma2(mB2, w.x, oB[2 * q + 0]);
                oB[2 * q + 1] = ffma2(mB2, w.y, oB[2 * q + 1]);
            }
        }
#pragma unroll
        for (int j = 0; j < 8; ++j) {
            float2 vA = up2(oA[j]);
            float2 vB = up2(oB[j]);
            lg[p0 * 33 + pass * 16 + 2 * j + 0] = vA.x;
            lg[p0 * 33 + pass * 16 + 2 * j + 1] = vA.y;
            lg[p1 * 33 + pass * 16 + 2 * j + 0] = vB.x;
            lg[p1 * 33 + pass * 16 + 2 * j + 1] = vB.y;
        }
    }
    __syncthreads();

    // softmax over p per channel; 8 warps, warp w handles channels 4w..4w+3
    const int w = tid >> 5, lane = tid & 31;
#pragma unroll
    for (int cc = 0; cc < 4; ++cc) {
        int c = w * 4 + cc;
        float mx = -3.4e38f;
#pragma unroll
        for (int i = 0; i < 16; ++i) mx = fmaxf(mx, lg[(lane + i * 32) * 33 + c]);
#pragma unroll
        for (int off = 16; off; off >>= 1) mx = fmaxf(mx, __shfl_xor_sync(0xffffffffu, mx, off));
        float ev[16]; float sum = 0.f;
#pragma unroll
        for (int i = 0; i < 16; ++i) {
            ev[i] = __expf(lg[(lane + i * 32) * 33 + c] - mx);
            sum += ev[i];
        }
#pragma unroll
        for (int off = 16; off; off >>= 1) sum += __shfl_xor_sync(0xffffffffu, sum, off);
        float inv = 1.0f / sum;
        size_t base = (((size_t)b * 32 + c) * 64 + l) * 512;
#pragma unroll
        for (int i = 0; i < 16; ++i) g_probs[base + lane + i * 32] = ev[i] * inv;
    }
}

// ---------------- out_pre[b,l,h,d] = sum_p probs[b,h,l,p] * cv[b,p,h,d] --------
__global__ void __launch_bounds__(256) outagg_kernel()
{
    const int b = blockIdx.x, h = blockIdx.y;
    __shared__ float Acs[64][128];
    __shared__ float Bcs[128][32];
    const int tid = threadIdx.x;
    const int d = tid & 31, lgp = tid >> 5, l0 = lgp * 8;
    float acc[8];
#pragma unroll
    for (int j = 0; j < 8; ++j) acc[j] = 0.f;

    for (int pc = 0; pc < 512; pc += 128) {
        __syncthreads();
        for (int e = tid; e < 2048; e += 256) {
            int l = e >> 5, pq = (e & 31) * 4;
            *(float4*)&Acs[l][pq] =
                *(const float4*)&g_probs[(((size_t)b * 32 + h) * 64 + l) * 512 + pc + pq];
        }
        for (int e = tid; e < 1024; e += 256) {
            int p = e >> 3, d4 = (e & 7) * 4;
            *(float4*)&Bcs[p][d4] =
                *(const float4*)&g_cv[((size_t)(b * 512 + pc + p)) * 512 + h * 32 + d4];
        }
        __syncthreads();
        for (int p = 0; p < 128; p += 4) {
            float bv0 = Bcs[p][d], bv1 = Bcs[p + 1][d], bv2 = Bcs[p + 2][d], bv3 = Bcs[p + 3][d];
#pragma unroll
            for (int j = 0; j < 8; ++j) {
                float4 a = *(const float4*)&Acs[l0 + j][p];
                acc[j] += a.x * bv0 + a.y * bv1 + a.z * bv2 + a.w * bv3;
            }
        }
    }
#pragma unroll
    for (int j = 0; j < 8; ++j)
        g_outpre[((size_t)(b * 64 + l0 + j)) * 512 + h * 32 + d] = acc[j];
}

// ---------------- distance path: aggregate + tiny MLP -------------------------
__global__ void __launch_bounds__(256) disagg_kernel(
    const float* __restrict__ xp, const float* __restrict__ xl,
    const float* __restrict__ w_dis1, const float* __restrict__ b_dis1,
    const float* __restrict__ w_dis2, const float* __restrict__ b_dis2,
    float* __restrict__ out)
{
    const int l = blockIdx.x, b = blockIdx.y;
    __shared__ float xps[512 * 3];
    __shared__ float ods[3][16];
    __shared__ float zs[3][32];
    const int tid = threadIdx.x;
    for (int e = tid; e < 1536; e += 256) xps[e] = xp[(size_t)b * 1536 + e];
    __syncthreads();

    const int w = tid >> 5, lane = tid & 31;
#pragma unroll
    for (int q = 0; q < 6; ++q) {
        int idx = w * 6 + q;
        int i = idx >> 4, h = idx & 15;
        size_t base = (((size_t)b * 32 + 16 + h) * 64 + l) * 512;
        float sum = 0.f;
#pragma unroll
        for (int it = 0; it < 16; ++it) {
            int p = lane + it * 32;
            sum += g_probs[base + p] * xps[p * 3 + i];
        }
#pragma unroll
        for (int off = 16; off; off >>= 1) sum += __shfl_xor_sync(0xffffffffu, sum, off);
        if (lane == 0) ods[i][h] = sum - xl[(size_t)(b * 64 + l) * 3 + i];
    }
    __syncthreads();
    if (tid < 96) {
        int i = tid >> 5, k = tid & 31;
        float hz = b_dis1[k];
#pragma unroll
        for (int j = 0; j < 16; ++j) hz += ods[i][j] * w_dis1[j * 32 + k];
        zs[i][k] = mishf(hz);
    }
    __syncthreads();
    if (tid < 48) {
        int i = tid / 16, h = tid % 16;
        float y = b_dis2[h];
#pragma unroll
        for (int k = 0; k < 32; ++k) y += zs[i][k] * w_dis2[k * 16 + h];
        out[OUT0 + (((size_t)b * 64 + l) * 3 + i) * 16 + h] = y;
    }
}

// ---------------- launch -------------------------------------------------------
extern "C" void kernel_launch(void* const* d_in, const int* in_sizes, int n_in,
                              void* d_out, int out_size)
{
    (void)in_sizes; (void)n_in; (void)out_size;
    const float* h_ligand = (const float*)d_in[0];
    const float* context  = (const float*)d_in[1];
    const float* xp       = (const float*)d_in[2];
    const float* xl       = (const float*)d_in[3];
    const float* w_qk     = (const float*)d_in[4];
    // d_in[5] = w_v (unused by the reference)
    const float* w_cqk    = (const float*)d_in[6];
    const float* w_cv     = (const float*)d_in[7];
    const float* w_mlp1   = (const float*)d_in[8];
    const float* w_mlp2   = (const float*)d_in[9];
    const float* b_mlp2   = (const float*)d_in[10];
    const float* w_out    = (const float*)d_in[11];
    const float* b_out    = (const float*)d_in[12];
    const float* w_dis1   = (const float*)d_in[13];
    const float* b_dis1   = (const float*)d_in[14];
    const float* w_dis2   = (const float*)d_in[15];
    const float* b_dis2   = (const float*)d_in[16];
    const float* sigma    = (const float*)d_in[17];
    const float* w_pe1    = (const float*)d_in[18];
    const float* b_pe1    = (const float*)d_in[19];
    const float* w_pe2    = (const float*)d_in[20];
    const float* b_pe2    = (const float*)d_in[21];
    float* out = (float*)d_out;

    void *p_qk, *p_cqk, *p_cv, *p_outpre;
    cudaGetSymbolAddress(&p_qk, g_qk);
    cudaGetSymbolAddress(&p_cqk, g_cqk);
    cudaGetSymbolAddress(&p_cv, g_cv);
    cudaGetSymbolAddress(&p_outpre, g_outpre);

    // #1 qk projection (tf32)
    tgemm_k<0><<<dim3(4, 8), 256>>>(h_ligand, w_qk, nullptr,
                                    (float*)p_qk, nullptr, 1024, 512, 128);
    // #2 cqk + cv projections fused in one launch (shared A = context)
    tgemm_k<1><<<dim3(8, 64), 256>>>(context, w_cqk, w_cv,
                                     (float*)p_cqk, (float*)p_cv, 8192, 512, 256);
    // #3 similarity scores (tf32 mma)
    sim_mma_kernel<<<dim3(2, 16, 16), 256>>>();

    // #4 fused pairwise MLPs + softmax  (profiled slot)
    const int sm4_bytes = SM4_FLOATS * (int)sizeof(float);
    cudaFuncSetAttribute(pair_kernel, cudaFuncAttributeMaxDynamicSharedMemorySize, sm4_bytes);
    pair_kernel<<<dim3(64, 16), 256, sm4_bytes>>>(xp, xl, w_mlp1, w_mlp2, b_mlp2,
                                                  sigma, w_pe1, b_pe1, w_pe2, b_pe2);

    // #5 context path: attn @ cv
    outagg_kernel<<<dim3(16, 16), 256>>>();
    // #6 out-proj (+bias) into d_out — 512 blocks
    outproj_kernel<<<512, 256>>>((const float*)p_outpre, w_out, b_out, out);
    // #7 distance path into d_out
    disagg_kernel<<<dim3(64, 16), 256>>>(xp, xl, w_dis1, b_dis1, w_dis2, b_dis2, out);
}

// round 7
// speedup vs baseline: 1.4772x; 1.1760x over previous
#include <cuda_runtime.h>
#include <cstddef>

#define OUT0 131072 // 1024*128, offset of out_dis in d_out

typedef unsigned long long u64;

// ---------------- scratch (device globals; no allocation allowed) -------------
__device__ float g_qk[1024 * 512];            // [B*L][INNER]
__device__ float g_cqk[8192 * 512];           // [B*P][INNER]
__device__ float g_cv[8192 * 512];            // [B*P][INNER]
__device__ float g_sim[16 * 16 * 64 * 512];   // [b][h][l][p] (scaled)
__device__ float g_probs[16 * 32 * 64 * 512]; // [b][c][l][p] (only c<16 written)
__device__ float g_outpre[1024 * 512];        // [B*L][INNER]

// mish(x) = x*tanh(softplus(x)) = x * u/(u+2), u = e^x*(e^x+2)  (exact identity)
__device__ __forceinline__ float mishf(float x) {
    float t = __expf(fminf(x, 8.0f));
    float u = t * (t + 2.0f);
    return x * __fdividef(u, u + 2.0f);
}

__device__ __forceinline__ float tf32r(float x) {
    unsigned u;
    asm("cvt.rna.tf32.f32 %0, %1;" : "=r"(u) : "f"(x));
    return __uint_as_float(u);
}

__device__ __forceinline__ void mma8(float* c, unsigned a0, unsigned a1,
                                     unsigned a2, unsigned a3,
                                     unsigned b0, unsigned b1) {
    asm volatile(
        "mma.sync.aligned.m16n8k8.row.col.f32.tf32.tf32.f32 "
        "{%0,%1,%2,%3},{%4,%5,%6,%7},{%8,%9},{%0,%1,%2,%3};"
        : "+f"(c[0]), "+f"(c[1]), "+f"(c[2]), "+f"(c[3])
        : "r"(a0), "r"(a1), "r"(a2), "r"(a3), "r"(b0), "r"(b1));
}

// ---- packed f32x2 helpers (Blackwell FFMA2 — only reachable via PTX) ---------
__device__ __forceinline__ u64 ffma2(u64 a, u64 b, u64 c) {
    u64 d;
    asm("fma.rn.f32x2 %0, %1, %2, %3;" : "=l"(d) : "l"(a), "l"(b), "l"(c));
    return d;
}
__device__ __forceinline__ u64 pk2(float x, float y) {
    u64 r;
    asm("mov.b64 %0, {%1, %2};" : "=l"(r) : "f"(x), "f"(y));
    return r;
}
__device__ __forceinline__ float2 up2(u64 v) {
    float2 r;
    asm("mov.b64 {%0, %1}, %2;" : "=f"(r.x), "=f"(r.y) : "l"(v));
    return r;
}

// ---------------- tf32 tensor-core GEMM: C[M,N] = A[M,K] @ B[K,N] -------------
// DUAL=1: N logically 1024 split across two 512-wide weight/output pairs.
template <int DUAL>
__global__ void __launch_bounds__(256) tgemm_k(
    const float* __restrict__ A, const float* __restrict__ B0,
    const float* __restrict__ B1, float* __restrict__ C0,
    float* __restrict__ C1, int M, int N, int K)
{
    __shared__ float As[128][36];
    __shared__ float Bs[32][136];
    const int tid = threadIdx.x;
    const int lane = tid & 31, warp = tid >> 5;
    const int wm = warp >> 1, wn = warp & 1;
    const int g = lane >> 2, t = lane & 3;
    const int row0 = blockIdx.y * 128;
    int col0 = blockIdx.x * 128;
    const float* Bm = B0;
    float* C = C0;
    if (DUAL && col0 >= 512) { Bm = B1; C = C1; col0 -= 512; }

    float acc[2][8][4];
#pragma unroll
    for (int mt = 0; mt < 2; ++mt)
#pragma unroll
        for (int nt = 0; nt < 8; ++nt)
#pragma unroll
            for (int q = 0; q < 4; ++q) acc[mt][nt][q] = 0.f;

    for (int k0 = 0; k0 < K; k0 += 32) {
        float4 va[4], vb[4];
#pragma unroll
        for (int i = 0; i < 4; ++i) {
            int f4 = tid + i * 256;
            int r = f4 >> 3, kc = (f4 & 7) * 4;
            va[i] = *(const float4*)&A[(size_t)(row0 + r) * K + k0 + kc];
            int kk = f4 >> 5, nc = (f4 & 31) * 4;
            vb[i] = *(const float4*)&Bm[(size_t)(k0 + kk) * N + col0 + nc];
        }
        __syncthreads();
#pragma unroll
        for (int i = 0; i < 4; ++i) {
            int f4 = tid + i * 256;
            int r = f4 >> 3, kc = (f4 & 7) * 4;
            As[r][kc + 0] = tf32r(va[i].x);
            As[r][kc + 1] = tf32r(va[i].y);
            As[r][kc + 2] = tf32r(va[i].z);
            As[r][kc + 3] = tf32r(va[i].w);
            int kk = f4 >> 5, nc = (f4 & 31) * 4;
            Bs[kk][nc + 0] = tf32r(vb[i].x);
            Bs[kk][nc + 1] = tf32r(vb[i].y);
            Bs[kk][nc + 2] = tf32r(vb[i].z);
            Bs[kk][nc + 3] = tf32r(vb[i].w);
        }
        __syncthreads();
#pragma unroll
        for (int ks = 0; ks < 4; ++ks) {
            const int kb = ks * 8;
            unsigned a[2][4];
#pragma unroll
            for (int mt = 0; mt < 2; ++mt) {
                int rb = wm * 32 + mt * 16;
                a[mt][0] = __float_as_uint(As[rb + g][kb + t]);
                a[mt][1] = __float_as_uint(As[rb + g + 8][kb + t]);
                a[mt][2] = __float_as_uint(As[rb + g][kb + t + 4]);
                a[mt][3] = __float_as_uint(As[rb + g + 8][kb + t + 4]);
            }
#pragma unroll
            for (int nt = 0; nt < 8; ++nt) {
                int nb = wn * 64 + nt * 8;
                unsigned b0 = __float_as_uint(Bs[kb + t][nb + g]);
                unsigned b1 = __float_as_uint(Bs[kb + t + 4][nb + g]);
#pragma unroll
                for (int mt = 0; mt < 2; ++mt)
                    mma8(acc[mt][nt], a[mt][0], a[mt][1], a[mt][2], a[mt][3], b0, b1);
            }
        }
    }
#pragma unroll
    for (int mt = 0; mt < 2; ++mt) {
#pragma unroll
        for (int nt = 0; nt < 8; ++nt) {
            int r = row0 + wm * 32 + mt * 16 + g;
            int c = col0 + wn * 64 + nt * 8 + 2 * t;
            *(float2*)&C[(size_t)r * N + c] = make_float2(acc[mt][nt][0], acc[mt][nt][1]);
            *(float2*)&C[(size_t)(r + 8) * N + c] = make_float2(acc[mt][nt][2], acc[mt][nt][3]);
        }
    }
}

// ---------------- out-proj: out[r][c] = outpre[r] . w_out[:,c] + b[c] ---------
__global__ void __launch_bounds__(256) outproj_kernel(
    const float* __restrict__ A, const float* __restrict__ B,
    const float* __restrict__ bias, float* __restrict__ C)
{
    __shared__ float As[2][512];
    const int tid = threadIdx.x;
    const int r0 = blockIdx.x * 2;
    {
        const float4* src = (const float4*)&A[(size_t)r0 * 512];
        float4* dst = (float4*)&As[0][0];
        dst[tid] = src[tid];
    }
    __syncthreads();
    const int row = tid >> 7, c = tid & 127;
    const float* arow = As[row];
    float acc = bias[c];
    const float* bp = B + c;
#pragma unroll 8
    for (int k = 0; k < 512; k += 4) {
        float4 a = *(const float4*)&arow[k];
        acc += a.x * bp[(size_t)(k + 0) * 128];
        acc += a.y * bp[(size_t)(k + 1) * 128];
        acc += a.z * bp[(size_t)(k + 2) * 128];
        acc += a.w * bp[(size_t)(k + 3) * 128];
    }
    C[(size_t)(r0 + row) * 128 + c] = acc;
}

// ---------------- sim via tf32 mma: per (p-half, h, b) 64x256x32 --------------
__global__ void __launch_bounds__(256) sim_mma_kernel()
{
    __shared__ float As[64 * 34];   // [l][d]
    __shared__ float Bs[32 * 258];  // [d][p] (transposed)
    const int ph = blockIdx.x, h = blockIdx.y, b = blockIdx.z;
    const int tid = threadIdx.x;
    const int w = tid >> 5, lane = tid & 31, g = lane >> 2, t = lane & 3;

    for (int e = tid; e < 2048; e += 256) {
        int lr = e >> 5, d = e & 31;
        As[lr * 34 + d] = tf32r(g_qk[((size_t)(b * 64 + lr)) * 512 + h * 32 + d]);
    }
    for (int e = tid; e < 8192; e += 256) {
        int p = e >> 5, d = e & 31;
        Bs[d * 258 + p] = tf32r(g_cqk[((size_t)(b * 512 + ph * 256 + p)) * 512 + h * 32 + d]);
    }
    __syncthreads();

    float acc[4][4][4];
#pragma unroll
    for (int mi = 0; mi < 4; ++mi)
#pragma unroll
        for (int nt = 0; nt < 4; ++nt)
#pragma unroll
            for (int q = 0; q < 4; ++q) acc[mi][nt][q] = 0.f;

    const int n0 = w * 32;
#pragma unroll
    for (int kt = 0; kt < 4; ++kt) {
        const int kb = kt * 8;
        unsigned aF[4][4];
#pragma unroll
        for (int mi = 0; mi < 4; ++mi) {
            int rA = mi * 16;
            aF[mi][0] = __float_as_uint(As[(rA + g) * 34 + kb + t]);
            aF[mi][1] = __float_as_uint(As[(rA + g + 8) * 34 + kb + t]);
            aF[mi][2] = __float_as_uint(As[(rA + g) * 34 + kb + t + 4]);
            aF[mi][3] = __float_as_uint(As[(rA + g + 8) * 34 + kb + t + 4]);
        }
#pragma unroll
        for (int nt = 0; nt < 4; ++nt) {
            int nb = n0 + nt * 8;
            unsigned b0 = __float_as_uint(Bs[(kb + t) * 258 + nb + g]);
            unsigned b1 = __float_as_uint(Bs[(kb + t + 4) * 258 + nb + g]);
#pragma unroll
            for (int mi = 0; mi < 4; ++mi)
                mma8(acc[mi][nt], aF[mi][0], aF[mi][1], aF[mi][2], aF[mi][3], b0, b1);
        }
    }
    const float SCALE = 0.17677669529663687f; // 32^-0.5
#pragma unroll
    for (int mi = 0; mi < 4; ++mi)
#pragma unroll
        for (int nt = 0; nt < 4; ++nt) {
            int lr = mi * 16 + g;
            int pc = ph * 256 + n0 + nt * 8 + 2 * t;
            size_t base = (((size_t)(b * 16 + h)) * 64 + lr) * 512 + pc;
            *(float2*)&g_sim[base] =
                make_float2(acc[mi][nt][0] * SCALE, acc[mi][nt][1] * SCALE);
            *(float2*)&g_sim[base + (size_t)8 * 512] =
                make_float2(acc[mi][nt][2] * SCALE, acc[mi][nt][3] * SCALE);
        }
}

// ------- fused pairwise MLPs + softmax + distance path (FFMA2, 2 p/thread) ----
#define SM4_FLOATS (512 * 33 + 2048 + 2048 + 256 + 1024 + 64 + 16 + 32 + 1536 + 48 + 96)
__global__ void __launch_bounds__(256) pair_kernel(
    const float* __restrict__ xp, const float* __restrict__ xl,
    const float* __restrict__ w_mlp1, const float* __restrict__ w_mlp2,
    const float* __restrict__ b_mlp2, const float* __restrict__ sigma,
    const float* __restrict__ w_pe1, const float* __restrict__ b_pe1,
    const float* __restrict__ w_pe2, const float* __restrict__ b_pe2,
    const float* __restrict__ w_dis1, const float* __restrict__ b_dis1,
    const float* __restrict__ w_dis2, const float* __restrict__ b_dis2,
    float* __restrict__ out)
{
    extern __shared__ float sm[];
    float* lg    = sm;                 // 512*33 logits -> probs(c>=16)
    float* w1t   = lg + 512 * 33;      // [k][i] transposed w_mlp1, 64*32
    float* w2s   = w1t + 2048;         // w_mlp2 as-is, 64*32
    float* wpe1t = w2s + 2048;         // [k][i(pad4)], 64*4
    float* wpe2s = wpe1t + 256;        // w_pe2 as-is, 64*16
    float* bpe1s = wpe2s + 1024;       // 64
    float* bpe2s = bpe1s + 64;         // 16
    float* bm2s  = bpe2s + 16;         // 32
    float* xps   = bm2s + 32;          // [512][3] raw protein coords
    float* ods   = xps + 1536;         // [3][16]
    float* zs    = ods + 48;           // [3][32]

    const int tid = threadIdx.x;
    const int l = blockIdx.x, b = blockIdx.y;

    for (int e = tid; e < 2048; e += 256) { int i = e >> 6, k = e & 63; w1t[k * 32 + i] = w_mlp1[e]; }
    for (int e = tid; e < 2048; e += 256) w2s[e] = w_mlp2[e];
    if (tid < 192) { int i = tid >> 6, k = tid & 63; wpe1t[k * 4 + i] = w_pe1[tid]; }
    for (int e = tid; e < 1024; e += 256) wpe2s[e] = w_pe2[e];
    if (tid < 64) bpe1s[tid] = b_pe1[tid];
    if (tid < 16) bpe2s[tid] = b_pe2[tid];
    if (tid < 32) bm2s[tid]  = b_mlp2[tid];
    __syncthreads();

    const float sg = sigma[0];
    const float cpe = -0.5f / (sg * sg);
    const int rowl = b * 64 + l;
    const float xl0 = xl[rowl * 3 + 0], xl1 = xl[rowl * 3 + 1], xl2 = xl[rowl * 3 + 2];

    const int p0 = tid, p1 = tid + 256;

    // s pairs for both p: [0..7] sim heads, [8..15] dis_emb
    u64 sp0[16], sp1[16];
    {
        size_t base = (((size_t)b * 16) * 64 + l) * 512;
#pragma unroll
        for (int h2 = 0; h2 < 8; ++h2) {
            size_t o0 = base + (size_t)(2 * h2) * 64 * 512;
            size_t o1 = base + (size_t)(2 * h2 + 1) * 64 * 512;
            sp0[h2] = pk2(g_sim[o0 + p0], g_sim[o1 + p0]);
            sp1[h2] = pk2(g_sim[o0 + p1], g_sim[o1 + p1]);
        }
    }

    // positional-encoding MLP: 3 -> 64 (mish) -> 16, both p share weight loads
    {
        const float* xpr0 = xp + (size_t)(b * 512 + p0) * 3;
        const float* xpr1 = xp + (size_t)(b * 512 + p1) * 3;
        float xA0 = xpr0[0], xA1 = xpr0[1], xA2 = xpr0[2];
        float xB0 = xpr1[0], xB1 = xpr1[1], xB2 = xpr1[2];
        // stash raw coords for the distance path
        xps[p0 * 3 + 0] = xA0; xps[p0 * 3 + 1] = xA1; xps[p0 * 3 + 2] = xA2;
        xps[p1 * 3 + 0] = xB0; xps[p1 * 3 + 1] = xB1; xps[p1 * 3 + 2] = xB2;

        float peA0 = __expf(cpe * (xA0 - xl0));
        float peA1 = __expf(cpe * (xA1 - xl1));
        float peA2 = __expf(cpe * (xA2 - xl2));
        float peB0 = __expf(cpe * (xB0 - xl0));
        float peB1 = __expf(cpe * (xB1 - xl1));
        float peB2 = __expf(cpe * (xB2 - xl2));

        u64 deA[8], deB[8];
#pragma unroll
        for (int j = 0; j < 8; ++j) {
            u64 bb = pk2(bpe2s[2 * j], bpe2s[2 * j + 1]);
            deA[j] = bb; deB[j] = bb;
        }
#pragma unroll 2
        for (int k = 0; k < 64; ++k) {
            float w0 = wpe1t[k * 4], w1 = wpe1t[k * 4 + 1], w2 = wpe1t[k * 4 + 2];
            float bk = bpe1s[k];
            float hA = bk + peA0 * w0 + peA1 * w1 + peA2 * w2;
            float hB = bk + peB0 * w0 + peB1 * w1 + peB2 * w2;
            float mA = mishf(hA), mB = mishf(hB);
            u64 mA2 = pk2(mA, mA), mB2 = pk2(mB, mB);
            const ulonglong2* wr = (const ulonglong2*)(wpe2s + k * 16);
#pragma unroll
            for (int q = 0; q < 4; ++q) {
                ulonglong2 w = wr[q];
                deA[2 * q + 0] = ffma2(mA2, w.x, deA[2 * q + 0]);
                deA[2 * q + 1] = ffma2(mA2, w.y, deA[2 * q + 1]);
                deB[2 * q + 0] = ffma2(mB2, w.x, deB[2 * q + 0]);
                deB[2 * q + 1] = ffma2(mB2, w.y, deB[2 * q + 1]);
            }
        }
#pragma unroll
        for (int j = 0; j < 8; ++j) { sp0[8 + j] = deA[j]; sp1[8 + j] = deB[j]; }
    }

    // attention MLP: 32 -> 64 (mish) -> 32, single pass, split h-chains for ILP
    const u64 z2 = pk2(0.f, 0.f);
    u64 oA[16], oB[16];
#pragma unroll
    for (int j = 0; j < 16; ++j) {
        u64 bb = pk2(bm2s[2 * j], bm2s[2 * j + 1]);
        oA[j] = bb; oB[j] = bb;
    }
#pragma unroll 2
    for (int k = 0; k < 64; ++k) {
        const ulonglong2* w1r = (const ulonglong2*)(w1t + k * 32);
        u64 hA0 = z2, hA1 = z2, hB0 = z2, hB1 = z2;
#pragma unroll
        for (int q = 0; q < 4; ++q) {
            ulonglong2 w = w1r[q];
            hA0 = ffma2(sp0[2 * q + 0], w.x, hA0);
            hA0 = ffma2(sp0[2 * q + 1], w.y, hA0);
            hB0 = ffma2(sp1[2 * q + 0], w.x, hB0);
            hB0 = ffma2(sp1[2 * q + 1], w.y, hB0);
        }
#pragma unroll
        for (int q = 4; q < 8; ++q) {
            ulonglong2 w = w1r[q];
            hA1 = ffma2(sp0[2 * q + 0], w.x, hA1);
            hA1 = ffma2(sp0[2 * q + 1], w.y, hA1);
            hB1 = ffma2(sp1[2 * q + 0], w.x, hB1);
            hB1 = ffma2(sp1[2 * q + 1], w.y, hB1);
        }
        float2 a0 = up2(hA0), a1 = up2(hA1);
        float2 b0 = up2(hB0), b1 = up2(hB1);
        float mA = mishf((a0.x + a0.y) + (a1.x + a1.y));
        float mB = mishf((b0.x + b0.y) + (b1.x + b1.y));
        u64 mA2 = pk2(mA, mA), mB2 = pk2(mB, mB);
        const ulonglong2* w2r = (const ulonglong2*)(w2s + k * 32);
#pragma unroll
        for (int q = 0; q < 8; ++q) {
            ulonglong2 w = w2r[q];
            oA[2 * q + 0] = ffma2(mA2, w.x, oA[2 * q + 0]);
            oA[2 * q + 1] = ffma2(mA2, w.y, oA[2 * q + 1]);
            oB[2 * q + 0] = ffma2(mB2, w.x, oB[2 * q + 0]);
            oB[2 * q + 1] = ffma2(mB2, w.y, oB[2 * q + 1]);
        }
    }
#pragma unroll
    for (int j = 0; j < 16; ++j) {
        float2 vA = up2(oA[j]);
        float2 vB = up2(oB[j]);
        lg[p0 * 33 + 2 * j + 0] = vA.x;
        lg[p0 * 33 + 2 * j + 1] = vA.y;
        lg[p1 * 33 + 2 * j + 0] = vB.x;
        lg[p1 * 33 + 2 * j + 1] = vB.y;
    }
    __syncthreads();

    // softmax: warp w owns channels 4w..4w+3; c<16 -> g_probs, c>=16 -> lg smem
    const int w = tid >> 5, lane = tid & 31;
#pragma unroll
    for (int cc = 0; cc < 4; ++cc) {
        int c = w * 4 + cc;
        float mx = -3.4e38f;
#pragma unroll
        for (int i = 0; i < 16; ++i) mx = fmaxf(mx, lg[(lane + i * 32) * 33 + c]);
#pragma unroll
        for (int off = 16; off; off >>= 1) mx = fmaxf(mx, __shfl_xor_sync(0xffffffffu, mx, off));
        float ev[16]; float sum = 0.f;
#pragma unroll
        for (int i = 0; i < 16; ++i) {
            ev[i] = __expf(lg[(lane + i * 32) * 33 + c] - mx);
            sum += ev[i];
        }
#pragma unroll
        for (int off = 16; off; off >>= 1) sum += __shfl_xor_sync(0xffffffffu, sum, off);
        float inv = 1.0f / sum;
        if (c < 16) {
            size_t base = (((size_t)b * 32 + c) * 64 + l) * 512;
#pragma unroll
            for (int i = 0; i < 16; ++i) g_probs[base + lane + i * 32] = ev[i] * inv;
        } else {
#pragma unroll
            for (int i = 0; i < 16; ++i) lg[(lane + i * 32) * 33 + c] = ev[i] * inv;
        }
    }
    __syncthreads();

    // ---- fused distance path: Σ_p prob·xp − xl, then tiny MLP into d_out ----
#pragma unroll
    for (int q = 0; q < 6; ++q) {
        int idx = w * 6 + q;
        int i = idx >> 4, h = idx & 15;
        float sum = 0.f;
#pragma unroll
        for (int it = 0; it < 16; ++it) {
            int p = lane + it * 32;
            sum += lg[p * 33 + 16 + h] * xps[p * 3 + i];
        }
#pragma unroll
        for (int off = 16; off; off >>= 1) sum += __shfl_xor_sync(0xffffffffu, sum, off);
        if (lane == 0) {
            float xli = (i == 0) ? xl0 : ((i == 1) ? xl1 : xl2);
            ods[i * 16 + h] = sum - xli;
        }
    }
    __syncthreads();
    if (tid < 96) {
        int i = tid >> 5, k = tid & 31;
        float hz = b_dis1[k];
#pragma unroll
        for (int j = 0; j < 16; ++j) hz += ods[i * 16 + j] * w_dis1[j * 32 + k];
        zs[i * 32 + k] = mishf(hz);
    }
    __syncthreads();
    if (tid < 48) {
        int i = tid / 16, h = tid % 16;
        float y = b_dis2[h];
#pragma unroll
        for (int k = 0; k < 32; ++k) y += zs[i * 32 + k] * w_dis2[k * 16 + h];
        out[OUT0 + (((size_t)b * 64 + l) * 3 + i) * 16 + h] = y;
    }
}

// ---------------- out_pre[b,l,h,d] = sum_p probs[b,h,l,p] * cv[b,p,h,d] --------
__global__ void __launch_bounds__(256) outagg_kernel()
{
    const int b = blockIdx.x, h = blockIdx.y;
    __shared__ float Acs[64][128];
    __shared__ float Bcs[128][32];
    const int tid = threadIdx.x;
    const int d = tid & 31, lgp = tid >> 5, l0 = lgp * 8;
    float acc[8];
#pragma unroll
    for (int j = 0; j < 8; ++j) acc[j] = 0.f;

    for (int pc = 0; pc < 512; pc += 128) {
        __syncthreads();
        for (int e = tid; e < 2048; e += 256) {
            int l = e >> 5, pq = (e & 31) * 4;
            *(float4*)&Acs[l][pq] =
                *(const float4*)&g_probs[(((size_t)b * 32 + h) * 64 + l) * 512 + pc + pq];
        }
        for (int e = tid; e < 1024; e += 256) {
            int p = e >> 3, d4 = (e & 7) * 4;
            *(float4*)&Bcs[p][d4] =
                *(const float4*)&g_cv[((size_t)(b * 512 + pc + p)) * 512 + h * 32 + d4];
        }
        __syncthreads();
        for (int p = 0; p < 128; p += 4) {
            float bv0 = Bcs[p][d], bv1 = Bcs[p + 1][d], bv2 = Bcs[p + 2][d], bv3 = Bcs[p + 3][d];
#pragma unroll
            for (int j = 0; j < 8; ++j) {
                float4 a = *(const float4*)&Acs[l0 + j][p];
                acc[j] += a.x * bv0 + a.y * bv1 + a.z * bv2 + a.w * bv3;
            }
        }
    }
#pragma unroll
    for (int j = 0; j < 8; ++j)
        g_outpre[((size_t)(b * 64 + l0 + j)) * 512 + h * 32 + d] = acc[j];
}

// ---------------- launch -------------------------------------------------------
extern "C" void kernel_launch(void* const* d_in, const int* in_sizes, int n_in,
                              void* d_out, int out_size)
{
    (void)in_sizes; (void)n_in; (void)out_size;
    const float* h_ligand = (const float*)d_in[0];
    const float* context  = (const float*)d_in[1];
    const float* xp       = (const float*)d_in[2];
    const float* xl       = (const float*)d_in[3];
    const float* w_qk     = (const float*)d_in[4];
    // d_in[5] = w_v (unused by the reference)
    const float* w_cqk    = (const float*)d_in[6];
    const float* w_cv     = (const float*)d_in[7];
    const float* w_mlp1   = (const float*)d_in[8];
    const float* w_mlp2   = (const float*)d_in[9];
    const float* b_mlp2   = (const float*)d_in[10];
    const float* w_out    = (const float*)d_in[11];
    const float* b_out    = (const float*)d_in[12];
    const float* w_dis1   = (const float*)d_in[13];
    const float* b_dis1   = (const float*)d_in[14];
    const float* w_dis2   = (const float*)d_in[15];
    const float* b_dis2   = (const float*)d_in[16];
    const float* sigma    = (const float*)d_in[17];
    const float* w_pe1    = (const float*)d_in[18];
    const float* b_pe1    = (const float*)d_in[19];
    const float* w_pe2    = (const float*)d_in[20];
    const float* b_pe2    = (const float*)d_in[21];
    float* out = (float*)d_out;

    void *p_qk, *p_cqk, *p_cv, *p_outpre;
    cudaGetSymbolAddress(&p_qk, g_qk);
    cudaGetSymbolAddress(&p_cqk, g_cqk);
    cudaGetSymbolAddress(&p_cv, g_cv);
    cudaGetSymbolAddress(&p_outpre, g_outpre);

    // #1 qk projection (tf32)
    tgemm_k<0><<<dim3(4, 8), 256>>>(h_ligand, w_qk, nullptr,
                                    (float*)p_qk, nullptr, 1024, 512, 128);
    // #2 cqk + cv projections fused in one launch (shared A = context)
    tgemm_k<1><<<dim3(8, 64), 256>>>(context, w_cqk, w_cv,
                                     (float*)p_cqk, (float*)p_cv, 8192, 512, 256);
    // #3 similarity scores (tf32 mma)
    sim_mma_kernel<<<dim3(2, 16, 16), 256>>>();

    // #4 fused pairwise MLPs + softmax + distance path (profiled slot)
    const int sm4_bytes = SM4_FLOATS * (int)sizeof(float);
    cudaFuncSetAttribute(pair_kernel, cudaFuncAttributeMaxDynamicSharedMemorySize, sm4_bytes);
    pair_kernel<<<dim3(64, 16), 256, sm4_bytes>>>(
        xp, xl, w_mlp1, w_mlp2, b_mlp2, sigma, w_pe1, b_pe1, w_pe2, b_pe2,
        w_dis1, b_dis1, w_dis2, b_dis2, out);

    // #5 context path: attn @ cv
    outagg_kernel<<<dim3(16, 16), 256>>>();
    // #6 out-proj (+bias) into d_out — 512 blocks
    outproj_kernel<<<512, 256>>>((const float*)p_outpre, w_out, b_out, out);
}